// round 7
// baseline (speedup 1.0000x reference)
#include <cuda_runtime.h>
#include <cstdint>

#define B_  4
#define LQ_ 2048
#define LK_ 2048
#define D_  1024

// ---------------- scratch (static device globals; no runtime alloc) ----------
__device__ float g_wt  [(size_t)3 * D_ * D_];        // W^T rounded, stacked
__device__ float g_bias[3 * D_];                     // biases stacked
__device__ float g_qkv [(size_t)3 * B_ * LQ_ * D_];  // projected q|k|v (tf32-rounded)
__device__ float g_vt  [(size_t)B_ * D_ * LK_];      // V^T per batch (tf32-rounded)
__device__ float g_s   [(size_t)B_ * LQ_ * LK_];     // scores / probs

// ---------------- PTX helpers ------------------------------------------------
__device__ __forceinline__ uint32_t smem_u32(const void* p) {
    uint32_t a;
    asm("{ .reg .u64 t; cvta.to.shared.u64 t, %1; cvt.u32.u64 %0, t; }" : "=r"(a) : "l"(p));
    return a;
}
__device__ __forceinline__ float rna_tf32(float x) {
    uint32_t r; asm("cvt.rna.tf32.f32 %0, %1;" : "=r"(r) : "f"(x));
    return __uint_as_float(r);
}
__device__ __forceinline__ uint32_t rna_tf32_u(uint32_t x) {
    uint32_t r; asm("cvt.rna.tf32.f32 %0, %1;" : "=r"(r) : "f"(__uint_as_float(x)));
    return r;
}
__device__ __forceinline__ void cp16(uint32_t s, const void* g) {
    asm volatile("cp.async.cg.shared.global [%0], [%1], 16;" :: "r"(s), "l"(g));
}
#define CP_COMMIT() asm volatile("cp.async.commit_group;" ::: "memory")
#define CP_WAIT(n)  asm volatile("cp.async.wait_group %0;" :: "n"(n) : "memory")

__device__ __forceinline__ void ldsm4(uint32_t* r, uint32_t addr) {
    asm volatile("ldmatrix.sync.aligned.m8n8.x4.shared.b16 {%0,%1,%2,%3}, [%4];"
        : "=r"(r[0]), "=r"(r[1]), "=r"(r[2]), "=r"(r[3]) : "r"(addr));
}

__device__ __forceinline__ void mma_tf32(float* c, const uint32_t* a, const uint32_t* b) {
    asm volatile(
        "mma.sync.aligned.m16n8k8.row.col.f32.tf32.tf32.f32 "
        "{%0,%1,%2,%3}, {%4,%5,%6,%7}, {%8,%9}, {%0,%1,%2,%3};"
        : "+f"(c[0]), "+f"(c[1]), "+f"(c[2]), "+f"(c[3])
        : "r"(a[0]), "r"(a[1]), "r"(a[2]), "r"(a[3]), "r"(b[0]), "r"(b[1]));
}

// ---------------- persistent tf32 mma.sync NT GEMM ---------------------------
// C[M,N] = alpha * A[M,K] @ Bt[N,K]^T (+ bias), tiles linearized over (x,y,z);
// each CTA walks tiles t = bid, bid+G, ... with a CONTINUOUS 3-stage cp.async
// pipeline across tile boundaries (epilogue overlapped with next tile's loads).
// Block tile 128x128x32; 128 threads = 4 warps (2x2), warp tile 64x64; 2 CTAs/SM.
#define BM 128
#define BN 128
#define BK 32
#define RST 36
#define STAGE_FLOATS ((BM + BN) * RST)   // 9216 floats = 36864 B
#define STAGES 3
#define GEMM_SMEM (STAGES * STAGE_FLOATS * 4)

template <bool MULTI_A, bool RND_A, bool BIAS, bool ROUND>
__global__ __launch_bounds__(128, 2)
void gemm_tf32(const float* __restrict__ A0, const float* __restrict__ A1,
               const float* __restrict__ A2, const float* __restrict__ Bt,
               const float* __restrict__ bias, float* __restrict__ C,
               int gx, int gxy, int ntile,
               int N, int K, float alpha,
               size_t sA, size_t sB, size_t sC, int sBias)
{
    extern __shared__ float smf[];
    const uint32_t sb32 = smem_u32(smf);

    const int tid  = threadIdx.x;
    const int wid  = tid >> 5;
    const int lane = tid & 31;
    const int grp  = lane >> 2;
    const int q    = lane & 3;
    const int wm   = wid & 1;
    const int wn   = wid >> 1;

    const int t0 = blockIdx.x;
    const int G  = gridDim.x;
    if (t0 >= ntile) return;

    const int KT = K / BK;

    // ldmatrix per-lane byte offsets
    const uint32_t aoff =
        ((wm * 64 + (lane & 7) + ((lane >> 3) & 1) * 8) * RST + ((lane >> 4) & 1) * 4) * 4;
    const uint32_t boff =
        ((wn * 64 + (lane & 7) + ((lane >> 4) & 1) * 8) * RST + ((lane >> 3) & 1) * 4) * 4;

    // ---- load cursor state ----
    int lt = t0, lkt = 0, ls = 0;
    const float* lA;
    const float* lB;
    int lm0, ln0;
    auto set_load_ctx = [&]() {
        const int z = lt / gxy;
        const int r = lt - z * gxy;
        lm0 = (r / gx) * BM;
        ln0 = (r - (r / gx) * gx) * BN;
        lA = MULTI_A ? (z == 0 ? A0 : (z == 1 ? A1 : A2)) : A0 + (size_t)z * sA;
        lB = Bt + (size_t)z * sB;
    };
    set_load_ctx();

    auto issue_load = [&]() {
        const uint32_t abase = sb32 + ls * STAGE_FLOATS * 4;
        const uint32_t bbase = abase + BM * RST * 4;
        const int k0 = lkt * BK;
#pragma unroll
        for (int j = 0; j < 8; j++) {
            const int idx = tid + j * 128;
            const int row = idx >> 3, seg = idx & 7;
            cp16(abase + (row * RST + seg * 4) * 4,
                 lA + (size_t)(lm0 + row) * K + k0 + seg * 4);
        }
#pragma unroll
        for (int j = 0; j < 8; j++) {
            const int idx = tid + j * 128;
            const int row = idx >> 3, seg = idx & 7;
            cp16(bbase + (row * RST + seg * 4) * 4,
                 lB + (size_t)(ln0 + row) * K + k0 + seg * 4);
        }
        CP_COMMIT();
        ls = (ls + 1 == STAGES) ? 0 : ls + 1;
        if (++lkt == KT) {
            lkt = 0; lt += G;
            if (lt < ntile) set_load_ctx();
        }
    };

    // prologue: 2 stages in flight
    int inflight = 0;
    issue_load(); inflight++;
    if (KT > 1 || lt < ntile) { issue_load(); inflight++; }

    int cs = 0;  // compute stage index

    float acc[4][8][4];

#pragma unroll 1
    for (int ct = t0; ct < ntile; ct += G) {
#pragma unroll
        for (int i = 0; i < 4; i++)
#pragma unroll
            for (int j = 0; j < 8; j++)
#pragma unroll
                for (int r = 0; r < 4; r++) acc[i][j][r] = 0.f;

#pragma unroll 1
        for (int kt = 0; kt < KT; kt++) {
            if (inflight >= 2) { CP_WAIT(1); } else { CP_WAIT(0); }
            inflight--;
            __syncthreads();
            if (lt < ntile) { issue_load(); inflight++; }

            const uint32_t sa = sb32 + cs * STAGE_FLOATS * 4;
            const uint32_t sbB = sa + BM * RST * 4;
            cs = (cs + 1 == STAGES) ? 0 : cs + 1;

#pragma unroll
            for (int kk = 0; kk < 4; kk++) {
                uint32_t af[4][4], bf[4][4];
#pragma unroll
                for (int mt = 0; mt < 4; mt++)
                    ldsm4(af[mt], sa + aoff + mt * (16 * RST * 4) + kk * 32);
                if (RND_A) {
#pragma unroll
                    for (int mt = 0; mt < 4; mt++)
#pragma unroll
                        for (int r = 0; r < 4; r++) af[mt][r] = rna_tf32_u(af[mt][r]);
                }
#pragma unroll
                for (int ntp = 0; ntp < 4; ntp++)
                    ldsm4(bf[ntp], sbB + boff + ntp * (16 * RST * 4) + kk * 32);
#pragma unroll
                for (int mt = 0; mt < 4; mt++)
#pragma unroll
                    for (int nt = 0; nt < 8; nt++)
                        mma_tf32(acc[mt][nt], af[mt], bf[nt >> 1] + (nt & 1) * 2);
            }
        }

        // epilogue for tile ct (overlaps next tile's in-flight loads)
        {
            const int z = ct / gxy;
            const int r0t = ct - z * gxy;
            const int cm0 = (r0t / gx) * BM;
            const int cn0 = (r0t - (r0t / gx) * gx) * BN;
            float* Cb = C + (size_t)z * sC;
            const float* biasb = BIAS ? (bias + (size_t)z * sBias) : nullptr;

#pragma unroll
            for (int mt = 0; mt < 4; mt++) {
                const int r = cm0 + wm * 64 + mt * 16 + grp;
#pragma unroll
                for (int nt = 0; nt < 8; nt++) {
                    const int c = cn0 + wn * 64 + nt * 8 + q * 2;
                    float2 v0, v1;
                    v0.x = acc[mt][nt][0] * alpha;
                    v0.y = acc[mt][nt][1] * alpha;
                    v1.x = acc[mt][nt][2] * alpha;
                    v1.y = acc[mt][nt][3] * alpha;
                    if (BIAS) {
                        const float2 bb = *(const float2*)(biasb + c);
                        v0.x += bb.x; v0.y += bb.y;
                        v1.x += bb.x; v1.y += bb.y;
                    }
                    if (ROUND) {
                        v0.x = rna_tf32(v0.x); v0.y = rna_tf32(v0.y);
                        v1.x = rna_tf32(v1.x); v1.y = rna_tf32(v1.y);
                    }
                    *(float2*)(Cb + (size_t)r * N + c)       = v0;
                    *(float2*)(Cb + (size_t)(r + 8) * N + c) = v1;
                }
            }
        }
    }
}

// ---------------- aux kernels ------------------------------------------------
// Batched: in[z] [R,C] row-major -> out + z*sOut [C,R] row-major, tf32-rounded.
__global__ __launch_bounds__(256)
void transpose3_round_k(const float* __restrict__ in0, const float* __restrict__ in1,
                        const float* __restrict__ in2, float* __restrict__ out,
                        int R, int C, size_t sIn, size_t sOut)
{
    __shared__ float t[32][33];
    const int z = blockIdx.z;
    const float* ib = (sIn ? in0 + (size_t)z * sIn
                           : (z == 0 ? in0 : (z == 1 ? in1 : in2)));
    float*       ob = out + (size_t)z * sOut;
    const int c0 = blockIdx.x * 32, r0 = blockIdx.y * 32;
    const int tx = threadIdx.x & 31, ty = threadIdx.x >> 5;
#pragma unroll
    for (int i = 0; i < 32; i += 8)
        t[ty + i][tx] = ib[(size_t)(r0 + ty + i) * C + c0 + tx];
    __syncthreads();
#pragma unroll
    for (int i = 0; i < 32; i += 8)
        ob[(size_t)(c0 + ty + i) * R + r0 + tx] = rna_tf32(t[tx][ty + i]);
}

// Row softmax over LK_ columns; tf32-rounded output.
__global__ __launch_bounds__(256)
void softmax_k(float* __restrict__ S)
{
    __shared__ float red[256];
    float* p = S + (size_t)blockIdx.x * LK_;
    const int tid = threadIdx.x;

    float v[8];
    *(float4*)(v)     = *(const float4*)(p + tid * 8);
    *(float4*)(v + 4) = *(const float4*)(p + tid * 8 + 4);

    float mx = v[0];
#pragma unroll
    for (int i = 1; i < 8; i++) mx = fmaxf(mx, v[i]);
    red[tid] = mx;
    __syncthreads();
    for (int s = 128; s > 0; s >>= 1) {
        if (tid < s) red[tid] = fmaxf(red[tid], red[tid + s]);
        __syncthreads();
    }
    mx = red[0];
    __syncthreads();

    float sum = 0.f;
#pragma unroll
    for (int i = 0; i < 8; i++) { v[i] = __expf(v[i] - mx); sum += v[i]; }
    red[tid] = sum;
    __syncthreads();
    for (int s = 128; s > 0; s >>= 1) {
        if (tid < s) red[tid] += red[tid + s];
        __syncthreads();
    }
    const float inv = 1.f / red[0];
    __syncthreads();

#pragma unroll
    for (int i = 0; i < 8; i++) v[i] = rna_tf32(v[i] * inv);
    *(float4*)(p + tid * 8)     = *(float4*)(v);
    *(float4*)(p + tid * 8 + 4) = *(float4*)(v + 4);
}

// ---------------- host -------------------------------------------------------
extern "C" void kernel_launch(void* const* d_in, const int* in_sizes, int n_in,
                              void* d_out, int out_size)
{
    const float* q_in = (const float*)d_in[0];
    const float* k_in = (const float*)d_in[1];
    const float* v_in = (const float*)d_in[2];
    const float* Wq   = (const float*)d_in[3];
    const float* bq   = (const float*)d_in[4];
    const float* Wk   = (const float*)d_in[5];
    const float* bk   = (const float*)d_in[6];
    const float* Wv   = (const float*)d_in[7];
    const float* bv   = (const float*)d_in[8];
    float* out = (float*)d_out;

    float *pwt, *pbias, *pqkv, *pvt, *ps;
    cudaGetSymbolAddress((void**)&pwt,   g_wt);
    cudaGetSymbolAddress((void**)&pbias, g_bias);
    cudaGetSymbolAddress((void**)&pqkv,  g_qkv);
    cudaGetSymbolAddress((void**)&pvt,   g_vt);
    cudaGetSymbolAddress((void**)&ps,    g_s);

    cudaFuncSetAttribute((const void*)gemm_tf32<true,  true,  true,  true >,
                         cudaFuncAttributeMaxDynamicSharedMemorySize, GEMM_SMEM);
    cudaFuncSetAttribute((const void*)gemm_tf32<false, false, false, false>,
                         cudaFuncAttributeMaxDynamicSharedMemorySize, GEMM_SMEM);

    int nsm = 148;
    cudaDeviceGetAttribute(&nsm, cudaDevAttrMultiProcessorCount, 0);
    const int G = 2 * nsm;  // persistent CTAs: 2 per SM

    const size_t T = (size_t)B_ * LQ_ * D_;

    // 1) W^T (rounded) batched, biases stacked
    transpose3_round_k<<<dim3(D_ / 32, D_ / 32, 3), 256>>>(
        Wq, Wk, Wv, pwt, D_, D_, 0, (size_t)D_ * D_);
    cudaMemcpyAsync(pbias + 0 * D_, bq, D_ * sizeof(float), cudaMemcpyDeviceToDevice);
    cudaMemcpyAsync(pbias + 1 * D_, bk, D_ * sizeof(float), cudaMemcpyDeviceToDevice);
    cudaMemcpyAsync(pbias + 2 * D_, bv, D_ * sizeof(float), cudaMemcpyDeviceToDevice);

    // 2) projections: tiles (x=D/BN, y=BLQ/BM, z=3)
    {
        const int gx = D_ / BN, gy = (B_ * LQ_) / BM, gz = 3;
        const int ntile = gx * gy * gz;
        gemm_tf32<true, true, true, true><<<G < ntile ? G : ntile, 128, GEMM_SMEM>>>(
            q_in, k_in, v_in, pwt, pbias, pqkv, gx, gx * gy, ntile,
            D_, D_, 1.f, 0, (size_t)D_ * D_, T, D_);
    }

    // 3) V^T per batch (rounded)
    transpose3_round_k<<<dim3(D_ / 32, LK_ / 32, B_), 256>>>(
        pqkv + 2 * T, nullptr, nullptr, pvt, LK_, D_, (size_t)LK_ * D_, (size_t)D_ * LK_);

    // 4) scores S = (Q K^T) / 32
    {
        const int gx = LK_ / BN, gy = LQ_ / BM, gz = B_;
        const int ntile = gx * gy * gz;
        gemm_tf32<false, false, false, false><<<G < ntile ? G : ntile, 128, GEMM_SMEM>>>(
            pqkv + 0 * T, nullptr, nullptr, pqkv + 1 * T, nullptr, ps, gx, gx * gy, ntile,
            LK_, D_, 1.f / 32.f,
            (size_t)LQ_ * D_, (size_t)LK_ * D_, (size_t)LQ_ * LK_, 0);
    }

    // 5) softmax rows (tf32-rounded probs)
    softmax_k<<<B_ * LQ_, 256>>>(ps);

    // 6) O = P @ V  (V^T is [D, LK] K-major)
    {
        const int gx = D_ / BN, gy = LQ_ / BM, gz = B_;
        const int ntile = gx * gy * gz;
        gemm_tf32<false, false, false, false><<<G < ntile ? G : ntile, 128, GEMM_SMEM>>>(
            ps, nullptr, nullptr, pvt, nullptr, out, gx, gx * gy, ntile,
            D_, LK_, 1.f,
            (size_t)LQ_ * LK_, (size_t)D_ * LK_, (size_t)LQ_ * D_, 0);
    }
}

// round 8
// speedup vs baseline: 1.1067x; 1.1067x over previous
#include <cuda_runtime.h>
#include <cstdint>

#define B_  4
#define LQ_ 2048
#define LK_ 2048
#define D_  1024

// ---------------- scratch (static device globals; no runtime alloc) ----------
__device__ float g_wt  [(size_t)3 * D_ * D_];        // W^T rounded, stacked
__device__ float g_bias[3 * D_];                     // biases stacked
__device__ float g_qkv [(size_t)3 * B_ * LQ_ * D_];  // projected q|k|v (tf32-rounded)
__device__ float g_vt  [(size_t)B_ * D_ * LK_];      // V^T per batch (tf32-rounded)
__device__ float g_s   [(size_t)B_ * LQ_ * LK_];     // scores / probs

// ---------------- PTX helpers ------------------------------------------------
__device__ __forceinline__ uint32_t smem_u32(const void* p) {
    uint32_t a;
    asm("{ .reg .u64 t; cvta.to.shared.u64 t, %1; cvt.u32.u64 %0, t; }" : "=r"(a) : "l"(p));
    return a;
}
__device__ __forceinline__ float rna_tf32(float x) {
    uint32_t r; asm("cvt.rna.tf32.f32 %0, %1;" : "=r"(r) : "f"(x));
    return __uint_as_float(r);
}
__device__ __forceinline__ uint32_t rna_tf32_u(uint32_t x) {
    uint32_t r; asm("cvt.rna.tf32.f32 %0, %1;" : "=r"(r) : "f"(__uint_as_float(x)));
    return r;
}
__device__ __forceinline__ void cp16(uint32_t s, const void* g) {
    asm volatile("cp.async.cg.shared.global [%0], [%1], 16;" :: "r"(s), "l"(g));
}
#define CP_COMMIT() asm volatile("cp.async.commit_group;" ::: "memory")
#define CP_WAIT(n)  asm volatile("cp.async.wait_group %0;" :: "n"(n) : "memory")

__device__ __forceinline__ void ldsm4(uint32_t* r, uint32_t addr) {
    asm volatile("ldmatrix.sync.aligned.m8n8.x4.shared.b16 {%0,%1,%2,%3}, [%4];"
        : "=r"(r[0]), "=r"(r[1]), "=r"(r[2]), "=r"(r[3]) : "r"(addr));
}

__device__ __forceinline__ void mma_tf32(float* c, const uint32_t* a, const uint32_t* b) {
    asm volatile(
        "mma.sync.aligned.m16n8k8.row.col.f32.tf32.tf32.f32 "
        "{%0,%1,%2,%3}, {%4,%5,%6,%7}, {%8,%9}, {%0,%1,%2,%3};"
        : "+f"(c[0]), "+f"(c[1]), "+f"(c[2]), "+f"(c[3])
        : "r"(a[0]), "r"(a[1]), "r"(a[2]), "r"(a[3]), "r"(b[0]), "r"(b[1]));
}

// ---------------- tf32 mma.sync NT GEMM --------------------------------------
// C[M,N] = alpha * A[M,K] @ Bt[N,K]^T (+ bias), batched via blockIdx.z.
// Block tile 128x128x32; 256 threads = 8 warps in 4(M) x 2(N); warp tile 32x64.
// ~120 regs/thread -> 2 CTAs/SM -> 16 warps/SM = 4 per SMSP (latency hiding).
#define BM 128
#define BN 128
#define BK 32
#define RST 36
#define STAGE_FLOATS ((BM + BN) * RST)   // 9216 floats = 36864 B
#define STAGES 3
#define GEMM_SMEM (STAGES * STAGE_FLOATS * 4)

template <bool MULTI_A, bool RND_A, bool BIAS, bool ROUND>
__global__ __launch_bounds__(256, 2)
void gemm_tf32(const float* __restrict__ A0, const float* __restrict__ A1,
               const float* __restrict__ A2, const float* __restrict__ Bt,
               const float* __restrict__ bias, float* __restrict__ C,
               int N, int K, float alpha,
               size_t sA, size_t sB, size_t sC, int sBias)
{
    extern __shared__ float smf[];
    const uint32_t sb32 = smem_u32(smf);

    const int tid  = threadIdx.x;
    const int wid  = tid >> 5;
    const int lane = tid & 31;
    const int grp  = lane >> 2;   // 0..7
    const int q    = lane & 3;    // 0..3
    const int wm   = wid & 3;     // 4 warps along M -> 32 rows each
    const int wn   = wid >> 2;    // 2 warps along N -> 64 cols each

    const int m0 = blockIdx.y * BM;
    const int n0 = blockIdx.x * BN;
    const int z  = blockIdx.z;

    const float* Ab = MULTI_A ? (z == 0 ? A0 : (z == 1 ? A1 : A2))
                              : A0 + (size_t)z * sA;
    const float* Bb = Bt + (size_t)z * sB;
    const float* biasb = BIAS ? (bias + (size_t)z * sBias) : nullptr;
    float* Cb = C + (size_t)z * sC;

    const int KT = K / BK;

    // per-lane ldmatrix byte offsets
    const uint32_t aoff =
        ((wm * 32 + (lane & 7) + ((lane >> 3) & 1) * 8) * RST + ((lane >> 4) & 1) * 4) * 4;
    const uint32_t boff =
        ((wn * 64 + (lane & 7) + ((lane >> 4) & 1) * 8) * RST + ((lane >> 3) & 1) * 4) * 4;

    // async load of one stage: A 128x32 + B 128x32, K-major rows (8 x 16B segs)
    auto load_stage = [&](int s, int kt) {
        const uint32_t abase = sb32 + s * STAGE_FLOATS * 4;
        const uint32_t bbase = abase + BM * RST * 4;
        const int k0 = kt * BK;
#pragma unroll
        for (int j = 0; j < 4; j++) {
            const int idx = tid + j * 256;          // 0..1023
            const int row = idx >> 3, seg = idx & 7;
            cp16(abase + (row * RST + seg * 4) * 4,
                 Ab + (size_t)(m0 + row) * K + k0 + seg * 4);
        }
#pragma unroll
        for (int j = 0; j < 4; j++) {
            const int idx = tid + j * 256;
            const int row = idx >> 3, seg = idx & 7;
            cp16(bbase + (row * RST + seg * 4) * 4,
                 Bb + (size_t)(n0 + row) * K + k0 + seg * 4);
        }
        CP_COMMIT();
    };

    float acc[2][8][4];
#pragma unroll
    for (int i = 0; i < 2; i++)
#pragma unroll
        for (int j = 0; j < 8; j++)
#pragma unroll
            for (int r = 0; r < 4; r++) acc[i][j][r] = 0.f;

    load_stage(0, 0);
    load_stage(1, 1);

    for (int kt = 0; kt < KT; kt++) {
        const int s = kt % STAGES;
        if (kt < KT - 1) { CP_WAIT(1); } else { CP_WAIT(0); }
        __syncthreads();

        if (kt + 2 < KT) load_stage((kt + 2) % STAGES, kt + 2);

        const uint32_t sa = sb32 + s * STAGE_FLOATS * 4;
        const uint32_t sbB = sa + BM * RST * 4;

#pragma unroll
        for (int kk = 0; kk < 4; kk++) {
            uint32_t af[2][4], bf[4][4];
#pragma unroll
            for (int mt = 0; mt < 2; mt++)
                ldsm4(af[mt], sa + aoff + mt * (16 * RST * 4) + kk * 32);
            if (RND_A) {
#pragma unroll
                for (int mt = 0; mt < 2; mt++)
#pragma unroll
                    for (int r = 0; r < 4; r++) af[mt][r] = rna_tf32_u(af[mt][r]);
            }
#pragma unroll
            for (int ntp = 0; ntp < 4; ntp++)
                ldsm4(bf[ntp], sbB + boff + ntp * (16 * RST * 4) + kk * 32);
#pragma unroll
            for (int mt = 0; mt < 2; mt++)
#pragma unroll
                for (int nt = 0; nt < 8; nt++)
                    mma_tf32(acc[mt][nt], af[mt], bf[nt >> 1] + (nt & 1) * 2);
        }
    }

    // Epilogue: acc[mt][nt] -> rows r, r+8 ; cols c..c+1
#pragma unroll
    for (int mt = 0; mt < 2; mt++) {
        const int r = m0 + wm * 32 + mt * 16 + grp;
#pragma unroll
        for (int nt = 0; nt < 8; nt++) {
            const int c = n0 + wn * 64 + nt * 8 + q * 2;
            float2 v0, v1;
            v0.x = acc[mt][nt][0] * alpha;
            v0.y = acc[mt][nt][1] * alpha;
            v1.x = acc[mt][nt][2] * alpha;
            v1.y = acc[mt][nt][3] * alpha;
            if (BIAS) {
                const float2 bb = *(const float2*)(biasb + c);
                v0.x += bb.x; v0.y += bb.y;
                v1.x += bb.x; v1.y += bb.y;
            }
            if (ROUND) {
                v0.x = rna_tf32(v0.x); v0.y = rna_tf32(v0.y);
                v1.x = rna_tf32(v1.x); v1.y = rna_tf32(v1.y);
            }
            *(float2*)(Cb + (size_t)r * N + c)       = v0;
            *(float2*)(Cb + (size_t)(r + 8) * N + c) = v1;
        }
    }
}

// ---------------- aux kernels ------------------------------------------------
// Batched: in[z] [R,C] row-major -> out + z*sOut [C,R] row-major, tf32-rounded.
__global__ __launch_bounds__(256)
void transpose3_round_k(const float* __restrict__ in0, const float* __restrict__ in1,
                        const float* __restrict__ in2, float* __restrict__ out,
                        int R, int C, size_t sIn, size_t sOut)
{
    __shared__ float t[32][33];
    const int z = blockIdx.z;
    const float* ib = (sIn ? in0 + (size_t)z * sIn
                           : (z == 0 ? in0 : (z == 1 ? in1 : in2)));
    float*       ob = out + (size_t)z * sOut;
    const int c0 = blockIdx.x * 32, r0 = blockIdx.y * 32;
    const int tx = threadIdx.x & 31, ty = threadIdx.x >> 5;
#pragma unroll
    for (int i = 0; i < 32; i += 8)
        t[ty + i][tx] = ib[(size_t)(r0 + ty + i) * C + c0 + tx];
    __syncthreads();
#pragma unroll
    for (int i = 0; i < 32; i += 8)
        ob[(size_t)(c0 + ty + i) * R + r0 + tx] = rna_tf32(t[tx][ty + i]);
}

// Row softmax over LK_ columns; tf32-rounded output.
__global__ __launch_bounds__(256)
void softmax_k(float* __restrict__ S)
{
    __shared__ float red[256];
    float* p = S + (size_t)blockIdx.x * LK_;
    const int tid = threadIdx.x;

    float v[8];
    *(float4*)(v)     = *(const float4*)(p + tid * 8);
    *(float4*)(v + 4) = *(const float4*)(p + tid * 8 + 4);

    float mx = v[0];
#pragma unroll
    for (int i = 1; i < 8; i++) mx = fmaxf(mx, v[i]);
    red[tid] = mx;
    __syncthreads();
    for (int s = 128; s > 0; s >>= 1) {
        if (tid < s) red[tid] = fmaxf(red[tid], red[tid + s]);
        __syncthreads();
    }
    mx = red[0];
    __syncthreads();

    float sum = 0.f;
#pragma unroll
    for (int i = 0; i < 8; i++) { v[i] = __expf(v[i] - mx); sum += v[i]; }
    red[tid] = sum;
    __syncthreads();
    for (int s = 128; s > 0; s >>= 1) {
        if (tid < s) red[tid] += red[tid + s];
        __syncthreads();
    }
    const float inv = 1.f / red[0];
    __syncthreads();

#pragma unroll
    for (int i = 0; i < 8; i++) v[i] = rna_tf32(v[i] * inv);
    *(float4*)(p + tid * 8)     = *(float4*)(v);
    *(float4*)(p + tid * 8 + 4) = *(float4*)(v + 4);
}

// ---------------- host -------------------------------------------------------
extern "C" void kernel_launch(void* const* d_in, const int* in_sizes, int n_in,
                              void* d_out, int out_size)
{
    const float* q_in = (const float*)d_in[0];
    const float* k_in = (const float*)d_in[1];
    const float* v_in = (const float*)d_in[2];
    const float* Wq   = (const float*)d_in[3];
    const float* bq   = (const float*)d_in[4];
    const float* Wk   = (const float*)d_in[5];
    const float* bk   = (const float*)d_in[6];
    const float* Wv   = (const float*)d_in[7];
    const float* bv   = (const float*)d_in[8];
    float* out = (float*)d_out;

    float *pwt, *pbias, *pqkv, *pvt, *ps;
    cudaGetSymbolAddress((void**)&pwt,   g_wt);
    cudaGetSymbolAddress((void**)&pbias, g_bias);
    cudaGetSymbolAddress((void**)&pqkv,  g_qkv);
    cudaGetSymbolAddress((void**)&pvt,   g_vt);
    cudaGetSymbolAddress((void**)&ps,    g_s);

    cudaFuncSetAttribute((const void*)gemm_tf32<true,  true,  true,  true >,
                         cudaFuncAttributeMaxDynamicSharedMemorySize, GEMM_SMEM);
    cudaFuncSetAttribute((const void*)gemm_tf32<false, false, false, false>,
                         cudaFuncAttributeMaxDynamicSharedMemorySize, GEMM_SMEM);

    const size_t T = (size_t)B_ * LQ_ * D_;

    // 1) W^T (rounded) batched, biases stacked
    transpose3_round_k<<<dim3(D_ / 32, D_ / 32, 3), 256>>>(
        Wq, Wk, Wv, pwt, D_, D_, 0, (size_t)D_ * D_);
    cudaMemcpyAsync(pbias + 0 * D_, bq, D_ * sizeof(float), cudaMemcpyDeviceToDevice);
    cudaMemcpyAsync(pbias + 1 * D_, bk, D_ * sizeof(float), cudaMemcpyDeviceToDevice);
    cudaMemcpyAsync(pbias + 2 * D_, bv, D_ * sizeof(float), cudaMemcpyDeviceToDevice);

    // 2) projections: batched over z (q|k|v), A rounded in-register, out rounded
    gemm_tf32<true, true, true, true><<<dim3(D_ / BN, (B_ * LQ_) / BM, 3), 256, GEMM_SMEM>>>(
        q_in, k_in, v_in, pwt, pbias, pqkv, D_, D_, 1.f,
        0, (size_t)D_ * D_, T, D_);

    // 3) V^T per batch (rounded)
    transpose3_round_k<<<dim3(D_ / 32, LK_ / 32, B_), 256>>>(
        pqkv + 2 * T, nullptr, nullptr, pvt, LK_, D_, (size_t)LK_ * D_, (size_t)D_ * LK_);

    // 4) scores S = (Q K^T) / 32
    gemm_tf32<false, false, false, false><<<dim3(LK_ / BN, LQ_ / BM, B_), 256, GEMM_SMEM>>>(
        pqkv + 0 * T, nullptr, nullptr, pqkv + 1 * T, nullptr, ps, LK_, D_, 1.f / 32.f,
        (size_t)LQ_ * D_, (size_t)LK_ * D_, (size_t)LQ_ * LK_, 0);

    // 5) softmax rows (tf32-rounded probs)
    softmax_k<<<B_ * LQ_, 256>>>(ps);

    // 6) O = P @ V  (V^T is [D, LK] K-major)
    gemm_tf32<false, false, false, false><<<dim3(D_ / BN, LQ_ / BM, B_), 256, GEMM_SMEM>>>(
        ps, nullptr, nullptr, pvt, nullptr, out, D_, LK_, 1.f,
        (size_t)LQ_ * LK_, (size_t)D_ * LK_, (size_t)LQ_ * D_, 0);
}

// round 9
// speedup vs baseline: 1.1331x; 1.0239x over previous
#include <cuda_runtime.h>
#include <cstdint>

#define B_  4
#define LQ_ 2048
#define LK_ 2048
#define D_  1024

// ---------------- scratch (static device globals; no runtime alloc) ----------
__device__ float g_wt  [(size_t)3 * D_ * D_];        // W^T rounded, stacked
__device__ float g_bias[3 * D_];                     // biases stacked
__device__ float g_qkv [(size_t)2 * B_ * LQ_ * D_];  // projected q|k (tf32-rounded)
__device__ float g_vt  [(size_t)B_ * D_ * LK_];      // V^T per batch (tf32-rounded)
__device__ float g_s   [(size_t)B_ * LQ_ * LK_];     // scores / probs

// ---------------- PTX helpers ------------------------------------------------
__device__ __forceinline__ uint32_t smem_u32(const void* p) {
    uint32_t a;
    asm("{ .reg .u64 t; cvta.to.shared.u64 t, %1; cvt.u32.u64 %0, t; }" : "=r"(a) : "l"(p));
    return a;
}
__device__ __forceinline__ float rna_tf32(float x) {
    uint32_t r; asm("cvt.rna.tf32.f32 %0, %1;" : "=r"(r) : "f"(x));
    return __uint_as_float(r);
}
__device__ __forceinline__ uint32_t rna_tf32_u(uint32_t x) {
    uint32_t r; asm("cvt.rna.tf32.f32 %0, %1;" : "=r"(r) : "f"(__uint_as_float(x)));
    return r;
}
__device__ __forceinline__ void cp16(uint32_t s, const void* g) {
    asm volatile("cp.async.cg.shared.global [%0], [%1], 16;" :: "r"(s), "l"(g));
}
#define CP_COMMIT() asm volatile("cp.async.commit_group;" ::: "memory")
#define CP_WAIT(n)  asm volatile("cp.async.wait_group %0;" :: "n"(n) : "memory")

__device__ __forceinline__ void ldsm4(uint32_t* r, uint32_t addr) {
    asm volatile("ldmatrix.sync.aligned.m8n8.x4.shared.b16 {%0,%1,%2,%3}, [%4];"
        : "=r"(r[0]), "=r"(r[1]), "=r"(r[2]), "=r"(r[3]) : "r"(addr));
}

__device__ __forceinline__ void mma_tf32(float* c, const uint32_t* a, const uint32_t* b) {
    asm volatile(
        "mma.sync.aligned.m16n8k8.row.col.f32.tf32.tf32.f32 "
        "{%0,%1,%2,%3}, {%4,%5,%6,%7}, {%8,%9}, {%0,%1,%2,%3};"
        : "+f"(c[0]), "+f"(c[1]), "+f"(c[2]), "+f"(c[3])
        : "r"(a[0]), "r"(a[1]), "r"(a[2]), "r"(a[3]), "r"(b[0]), "r"(b[1]));
}

// ---------------- tf32 mma.sync NT GEMM --------------------------------------
// C[M,N] = alpha * A[M,K] @ Bt[N,K]^T (+ bias), batched via blockIdx.z.
// Block tile 128x128x32; 256 threads = 8 warps in 4(M) x 2(N); warp tile 32x64.
// 128 regs/thread -> 2 CTAs/SM -> 16 warps/SM = 4 per SMSP.
// TRANSC: for z==zTrans, epilogue writes C transposed into Ct ([D, LK] per batch).
#define BM 128
#define BN 128
#define BK 32
#define RST 36
#define STAGE_FLOATS ((BM + BN) * RST)   // 9216 floats = 36864 B
#define STAGES 3
#define GEMM_SMEM (STAGES * STAGE_FLOATS * 4)

template <bool MULTI_A, bool RND_A, bool BIAS, bool ROUND, bool TRANSC>
__global__ __launch_bounds__(256, 2)
void gemm_tf32(const float* __restrict__ A0, const float* __restrict__ A1,
               const float* __restrict__ A2, const float* __restrict__ Bt,
               const float* __restrict__ bias, float* __restrict__ C,
               float* __restrict__ Ct, int zTrans,
               int N, int K, float alpha,
               size_t sA, size_t sB, size_t sC, int sBias)
{
    extern __shared__ float smf[];
    const uint32_t sb32 = smem_u32(smf);

    const int tid  = threadIdx.x;
    const int wid  = tid >> 5;
    const int lane = tid & 31;
    const int grp  = lane >> 2;   // 0..7
    const int q    = lane & 3;    // 0..3
    const int wm   = wid & 3;     // 4 warps along M -> 32 rows each
    const int wn   = wid >> 2;    // 2 warps along N -> 64 cols each

    const int m0 = blockIdx.y * BM;
    const int n0 = blockIdx.x * BN;
    const int z  = blockIdx.z;

    const float* Ab = MULTI_A ? (z == 0 ? A0 : (z == 1 ? A1 : A2))
                              : A0 + (size_t)z * sA;
    const float* Bb = Bt + (size_t)z * sB;
    const float* biasb = BIAS ? (bias + (size_t)z * sBias) : nullptr;
    float* Cb = C + (size_t)z * sC;

    const int KT = K / BK;

    // per-lane ldmatrix byte offsets
    const uint32_t aoff =
        ((wm * 32 + (lane & 7) + ((lane >> 3) & 1) * 8) * RST + ((lane >> 4) & 1) * 4) * 4;
    const uint32_t boff =
        ((wn * 64 + (lane & 7) + ((lane >> 4) & 1) * 8) * RST + ((lane >> 3) & 1) * 4) * 4;

    // async load of one stage: A 128x32 + B 128x32, K-major rows (8 x 16B segs)
    auto load_stage = [&](int s, int kt) {
        const uint32_t abase = sb32 + s * STAGE_FLOATS * 4;
        const uint32_t bbase = abase + BM * RST * 4;
        const int k0 = kt * BK;
#pragma unroll
        for (int j = 0; j < 4; j++) {
            const int idx = tid + j * 256;          // 0..1023
            const int row = idx >> 3, seg = idx & 7;
            cp16(abase + (row * RST + seg * 4) * 4,
                 Ab + (size_t)(m0 + row) * K + k0 + seg * 4);
        }
#pragma unroll
        for (int j = 0; j < 4; j++) {
            const int idx = tid + j * 256;
            const int row = idx >> 3, seg = idx & 7;
            cp16(bbase + (row * RST + seg * 4) * 4,
                 Bb + (size_t)(n0 + row) * K + k0 + seg * 4);
        }
        CP_COMMIT();
    };

    float acc[2][8][4];
#pragma unroll
    for (int i = 0; i < 2; i++)
#pragma unroll
        for (int j = 0; j < 8; j++)
#pragma unroll
            for (int r = 0; r < 4; r++) acc[i][j][r] = 0.f;

    load_stage(0, 0);
    load_stage(1, 1);

    for (int kt = 0; kt < KT; kt++) {
        const int s = kt % STAGES;
        if (kt < KT - 1) { CP_WAIT(1); } else { CP_WAIT(0); }
        __syncthreads();

        if (kt + 2 < KT) load_stage((kt + 2) % STAGES, kt + 2);

        const uint32_t sa = sb32 + s * STAGE_FLOATS * 4;
        const uint32_t sbB = sa + BM * RST * 4;

#pragma unroll
        for (int kk = 0; kk < 4; kk++) {
            uint32_t af[2][4], bf[4][4];
#pragma unroll
            for (int mt = 0; mt < 2; mt++)
                ldsm4(af[mt], sa + aoff + mt * (16 * RST * 4) + kk * 32);
            if (RND_A) {
#pragma unroll
                for (int mt = 0; mt < 2; mt++)
#pragma unroll
                    for (int r = 0; r < 4; r++) af[mt][r] = rna_tf32_u(af[mt][r]);
            }
#pragma unroll
            for (int ntp = 0; ntp < 4; ntp++)
                ldsm4(bf[ntp], sbB + boff + ntp * (16 * RST * 4) + kk * 32);
#pragma unroll
            for (int mt = 0; mt < 2; mt++)
#pragma unroll
                for (int nt = 0; nt < 8; nt++)
                    mma_tf32(acc[mt][nt], af[mt], bf[nt >> 1] + (nt & 1) * 2);
        }
    }

    // Epilogue
    const bool doTrans = TRANSC && (z == zTrans);
#pragma unroll
    for (int mt = 0; mt < 2; mt++) {
        const int r = m0 + wm * 32 + mt * 16 + grp;
#pragma unroll
        for (int nt = 0; nt < 8; nt++) {
            const int c = n0 + wn * 64 + nt * 8 + q * 2;
            float2 v0, v1;
            v0.x = acc[mt][nt][0] * alpha;
            v0.y = acc[mt][nt][1] * alpha;
            v1.x = acc[mt][nt][2] * alpha;
            v1.y = acc[mt][nt][3] * alpha;
            if (BIAS) {
                const float2 bb = *(const float2*)(biasb + c);
                v0.x += bb.x; v0.y += bb.y;
                v1.x += bb.x; v1.y += bb.y;
            }
            if (ROUND) {
                v0.x = rna_tf32(v0.x); v0.y = rna_tf32(v0.y);
                v1.x = rna_tf32(v1.x); v1.y = rna_tf32(v1.y);
            }
            if (doTrans) {
                // rows r, r+8 are (batch b, seq l); write Ct[b][c][l] (Ct: [D, LK] per batch)
                const int b0 = r >> 11,       l0 = r & 2047;
                const int b1 = (r + 8) >> 11, l1 = (r + 8) & 2047;
                float* t0 = Ct + (size_t)b0 * D_ * LK_ + l0;
                float* t1 = Ct + (size_t)b1 * D_ * LK_ + l1;
                t0[(size_t)(c)     * LK_] = v0.x;
                t0[(size_t)(c + 1) * LK_] = v0.y;
                t1[(size_t)(c)     * LK_] = v1.x;
                t1[(size_t)(c + 1) * LK_] = v1.y;
            } else {
                *(float2*)(Cb + (size_t)r * N + c)       = v0;
                *(float2*)(Cb + (size_t)(r + 8) * N + c) = v1;
            }
        }
    }
}

// ---------------- aux kernels ------------------------------------------------
// Batched: in[z] [R,C] row-major -> out + z*sOut [C,R] row-major, tf32-rounded.
__global__ __launch_bounds__(256)
void transpose3_round_k(const float* __restrict__ in0, const float* __restrict__ in1,
                        const float* __restrict__ in2, float* __restrict__ out,
                        int R, int C, size_t sOut)
{
    __shared__ float t[32][33];
    const int z = blockIdx.z;
    const float* ib = (z == 0 ? in0 : (z == 1 ? in1 : in2));
    float*       ob = out + (size_t)z * sOut;
    const int c0 = blockIdx.x * 32, r0 = blockIdx.y * 32;
    const int tx = threadIdx.x & 31, ty = threadIdx.x >> 5;
#pragma unroll
    for (int i = 0; i < 32; i += 8)
        t[ty + i][tx] = ib[(size_t)(r0 + ty + i) * C + c0 + tx];
    __syncthreads();
#pragma unroll
    for (int i = 0; i < 32; i += 8)
        ob[(size_t)(c0 + ty + i) * R + r0 + tx] = rna_tf32(t[tx][ty + i]);
}

// Copy 3 bias vectors (D_ floats each) into stacked g_bias.
__global__ __launch_bounds__(256)
void bias_copy_k(const float* __restrict__ b0, const float* __restrict__ b1,
                 const float* __restrict__ b2, float* __restrict__ out)
{
    const int i = blockIdx.x * 256 + threadIdx.x;  // 0..3*D_-1
    if (i < 3 * D_) {
        const int z = i / D_, j = i - z * D_;
        const float* src = (z == 0 ? b0 : (z == 1 ? b1 : b2));
        out[i] = src[j];
    }
}

// Row softmax over LK_ columns; tf32-rounded output.
__global__ __launch_bounds__(256)
void softmax_k(float* __restrict__ S)
{
    __shared__ float red[256];
    float* p = S + (size_t)blockIdx.x * LK_;
    const int tid = threadIdx.x;

    float v[8];
    *(float4*)(v)     = *(const float4*)(p + tid * 8);
    *(float4*)(v + 4) = *(const float4*)(p + tid * 8 + 4);

    float mx = v[0];
#pragma unroll
    for (int i = 1; i < 8; i++) mx = fmaxf(mx, v[i]);
    red[tid] = mx;
    __syncthreads();
    for (int s = 128; s > 0; s >>= 1) {
        if (tid < s) red[tid] = fmaxf(red[tid], red[tid + s]);
        __syncthreads();
    }
    mx = red[0];
    __syncthreads();

    float sum = 0.f;
#pragma unroll
    for (int i = 0; i < 8; i++) { v[i] = __expf(v[i] - mx); sum += v[i]; }
    red[tid] = sum;
    __syncthreads();
    for (int s = 128; s > 0; s >>= 1) {
        if (tid < s) red[tid] += red[tid + s];
        __syncthreads();
    }
    const float inv = 1.f / red[0];
    __syncthreads();

#pragma unroll
    for (int i = 0; i < 8; i++) v[i] = rna_tf32(v[i] * inv);
    *(float4*)(p + tid * 8)     = *(float4*)(v);
    *(float4*)(p + tid * 8 + 4) = *(float4*)(v + 4);
}

// ---------------- host -------------------------------------------------------
extern "C" void kernel_launch(void* const* d_in, const int* in_sizes, int n_in,
                              void* d_out, int out_size)
{
    const float* q_in = (const float*)d_in[0];
    const float* k_in = (const float*)d_in[1];
    const float* v_in = (const float*)d_in[2];
    const float* Wq   = (const float*)d_in[3];
    const float* bq   = (const float*)d_in[4];
    const float* Wk   = (const float*)d_in[5];
    const float* bk   = (const float*)d_in[6];
    const float* Wv   = (const float*)d_in[7];
    const float* bv   = (const float*)d_in[8];
    float* out = (float*)d_out;

    float *pwt, *pbias, *pqkv, *pvt, *ps;
    cudaGetSymbolAddress((void**)&pwt,   g_wt);
    cudaGetSymbolAddress((void**)&pbias, g_bias);
    cudaGetSymbolAddress((void**)&pqkv,  g_qkv);
    cudaGetSymbolAddress((void**)&pvt,   g_vt);
    cudaGetSymbolAddress((void**)&ps,    g_s);

    cudaFuncSetAttribute((const void*)gemm_tf32<true,  true,  true,  true,  true >,
                         cudaFuncAttributeMaxDynamicSharedMemorySize, GEMM_SMEM);
    cudaFuncSetAttribute((const void*)gemm_tf32<false, false, false, false, false>,
                         cudaFuncAttributeMaxDynamicSharedMemorySize, GEMM_SMEM);

    const size_t T = (size_t)B_ * LQ_ * D_;

    // 1) W^T (rounded) batched; biases stacked (single small kernel)
    transpose3_round_k<<<dim3(D_ / 32, D_ / 32, 3), 256>>>(
        Wq, Wk, Wv, pwt, D_, D_, (size_t)D_ * D_);
    bias_copy_k<<<(3 * D_ + 255) / 256, 256>>>(bq, bk, bv, pbias);

    // 2) projections: z=0 (Q), z=1 (K) -> g_qkv; z=2 (V) -> transposed into g_vt
    gemm_tf32<true, true, true, true, true><<<dim3(D_ / BN, (B_ * LQ_) / BM, 3), 256, GEMM_SMEM>>>(
        q_in, k_in, v_in, pwt, pbias, pqkv, pvt, /*zTrans=*/2, D_, D_, 1.f,
        0, (size_t)D_ * D_, T, D_);

    // 3) scores S = (Q K^T) / 32
    gemm_tf32<false, false, false, false, false><<<dim3(LK_ / BN, LQ_ / BM, B_), 256, GEMM_SMEM>>>(
        pqkv + 0 * T, nullptr, nullptr, pqkv + 1 * T, nullptr, ps, nullptr, -1,
        LK_, D_, 1.f / 32.f,
        (size_t)LQ_ * D_, (size_t)LK_ * D_, (size_t)LQ_ * LK_, 0);

    // 4) softmax rows (tf32-rounded probs)
    softmax_k<<<B_ * LQ_, 256>>>(ps);

    // 5) O = P @ V  (V^T is [D, LK] K-major)
    gemm_tf32<false, false, false, false, false><<<dim3(D_ / BN, LQ_ / BM, B_), 256, GEMM_SMEM>>>(
        ps, nullptr, nullptr, pvt, nullptr, out, nullptr, -1,
        D_, LK_, 1.f,
        (size_t)LQ_ * LK_, (size_t)D_ * LK_, (size_t)LQ_ * D_, 0);
}

// round 10
// speedup vs baseline: 1.1912x; 1.0513x over previous
#include <cuda_runtime.h>
#include <cstdint>

#define B_  4
#define LQ_ 2048
#define LK_ 2048
#define D_  1024

// ---------------- scratch (static device globals; no runtime alloc) ----------
__device__ float g_wt  [(size_t)2 * D_ * D_];        // slot0: Mt=Wk@Wq^T ; slot1: Wv^T
__device__ float g_bias[2 * D_];                     // slot0: zeros ; slot1: bv
__device__ float g_y   [(size_t)B_ * LQ_ * D_];      // Y = Xq @ M (tf32-rounded)
__device__ float g_vt  [(size_t)B_ * D_ * LK_];      // V^T per batch (tf32-rounded)
__device__ float g_s   [(size_t)B_ * LQ_ * LK_];     // scores / probs
__device__ float g_w   [D_];                         // w = Wk @ bq
__device__ float g_beta[(size_t)B_ * LK_];           // beta_j / 32 per key position

// ---------------- PTX helpers ------------------------------------------------
__device__ __forceinline__ uint32_t smem_u32(const void* p) {
    uint32_t a;
    asm("{ .reg .u64 t; cvta.to.shared.u64 t, %1; cvt.u32.u64 %0, t; }" : "=r"(a) : "l"(p));
    return a;
}
__device__ __forceinline__ float rna_tf32(float x) {
    uint32_t r; asm("cvt.rna.tf32.f32 %0, %1;" : "=r"(r) : "f"(x));
    return __uint_as_float(r);
}
__device__ __forceinline__ uint32_t rna_tf32_u(uint32_t x) {
    uint32_t r; asm("cvt.rna.tf32.f32 %0, %1;" : "=r"(r) : "f"(__uint_as_float(x)));
    return r;
}
__device__ __forceinline__ void cp16(uint32_t s, const void* g) {
    asm volatile("cp.async.cg.shared.global [%0], [%1], 16;" :: "r"(s), "l"(g));
}
#define CP_COMMIT() asm volatile("cp.async.commit_group;" ::: "memory")
#define CP_WAIT(n)  asm volatile("cp.async.wait_group %0;" :: "n"(n) : "memory")

__device__ __forceinline__ void ldsm4(uint32_t* r, uint32_t addr) {
    asm volatile("ldmatrix.sync.aligned.m8n8.x4.shared.b16 {%0,%1,%2,%3}, [%4];"
        : "=r"(r[0]), "=r"(r[1]), "=r"(r[2]), "=r"(r[3]) : "r"(addr));
}

__device__ __forceinline__ void mma_tf32(float* c, const uint32_t* a, const uint32_t* b) {
    asm volatile(
        "mma.sync.aligned.m16n8k8.row.col.f32.tf32.tf32.f32 "
        "{%0,%1,%2,%3}, {%4,%5,%6,%7}, {%8,%9}, {%0,%1,%2,%3};"
        : "+f"(c[0]), "+f"(c[1]), "+f"(c[2]), "+f"(c[3])
        : "r"(a[0]), "r"(a[1]), "r"(a[2]), "r"(a[3]), "r"(b[0]), "r"(b[1]));
}

// ---------------- tf32 mma.sync NT GEMM --------------------------------------
// C[M,N] = alpha * A[M,K] @ Bt[N,K]^T (+ bias), batched via blockIdx.z.
// Block tile 128x128x32; 256 threads = 8 warps in 4(M) x 2(N); warp tile 32x64.
// 128 regs/thread -> 2 CTAs/SM -> 16 warps/SM = 4 per SMSP.
// RND_A/RND_B: rna-round A/B fragments in-register (for raw fp32 operands).
// TRANSC: for z==zTrans, epilogue writes C transposed into Ct ([D, LK] per batch).
#define BM 128
#define BN 128
#define BK 32
#define RST 36
#define STAGE_FLOATS ((BM + BN) * RST)   // 9216 floats = 36864 B
#define STAGES 3
#define GEMM_SMEM (STAGES * STAGE_FLOATS * 4)

template <bool MULTI_A, bool RND_A, bool RND_B, bool BIAS, bool ROUND, bool TRANSC>
__global__ __launch_bounds__(256, 2)
void gemm_tf32(const float* __restrict__ A0, const float* __restrict__ A1,
               const float* __restrict__ Bt,
               const float* __restrict__ bias, float* __restrict__ C,
               float* __restrict__ Ct, int zTrans,
               int N, int K, float alpha,
               size_t sA, size_t sB, size_t sC, int sBias)
{
    extern __shared__ float smf[];
    const uint32_t sb32 = smem_u32(smf);

    const int tid  = threadIdx.x;
    const int wid  = tid >> 5;
    const int lane = tid & 31;
    const int grp  = lane >> 2;   // 0..7
    const int q    = lane & 3;    // 0..3
    const int wm   = wid & 3;     // 4 warps along M -> 32 rows each
    const int wn   = wid >> 2;    // 2 warps along N -> 64 cols each

    const int m0 = blockIdx.y * BM;
    const int n0 = blockIdx.x * BN;
    const int z  = blockIdx.z;

    const float* Ab = MULTI_A ? (z == 0 ? A0 : A1) : A0 + (size_t)z * sA;
    const float* Bb = Bt + (size_t)z * sB;
    const float* biasb = BIAS ? (bias + (size_t)z * sBias) : nullptr;
    float* Cb = C + (size_t)z * sC;

    const int KT = K / BK;

    // per-lane ldmatrix byte offsets
    const uint32_t aoff =
        ((wm * 32 + (lane & 7) + ((lane >> 3) & 1) * 8) * RST + ((lane >> 4) & 1) * 4) * 4;
    const uint32_t boff =
        ((wn * 64 + (lane & 7) + ((lane >> 4) & 1) * 8) * RST + ((lane >> 3) & 1) * 4) * 4;

    // async load of one stage: A 128x32 + B 128x32, K-major rows (8 x 16B segs)
    auto load_stage = [&](int s, int kt) {
        const uint32_t abase = sb32 + s * STAGE_FLOATS * 4;
        const uint32_t bbase = abase + BM * RST * 4;
        const int k0 = kt * BK;
#pragma unroll
        for (int j = 0; j < 4; j++) {
            const int idx = tid + j * 256;          // 0..1023
            const int row = idx >> 3, seg = idx & 7;
            cp16(abase + (row * RST + seg * 4) * 4,
                 Ab + (size_t)(m0 + row) * K + k0 + seg * 4);
        }
#pragma unroll
        for (int j = 0; j < 4; j++) {
            const int idx = tid + j * 256;
            const int row = idx >> 3, seg = idx & 7;
            cp16(bbase + (row * RST + seg * 4) * 4,
                 Bb + (size_t)(n0 + row) * K + k0 + seg * 4);
        }
        CP_COMMIT();
    };

    float acc[2][8][4];
#pragma unroll
    for (int i = 0; i < 2; i++)
#pragma unroll
        for (int j = 0; j < 8; j++)
#pragma unroll
            for (int r = 0; r < 4; r++) acc[i][j][r] = 0.f;

    load_stage(0, 0);
    load_stage(1, 1);

    for (int kt = 0; kt < KT; kt++) {
        const int s = kt % STAGES;
        if (kt < KT - 1) { CP_WAIT(1); } else { CP_WAIT(0); }
        __syncthreads();

        if (kt + 2 < KT) load_stage((kt + 2) % STAGES, kt + 2);

        const uint32_t sa = sb32 + s * STAGE_FLOATS * 4;
        const uint32_t sbB = sa + BM * RST * 4;

#pragma unroll
        for (int kk = 0; kk < 4; kk++) {
            uint32_t af[2][4], bf[4][4];
#pragma unroll
            for (int mt = 0; mt < 2; mt++)
                ldsm4(af[mt], sa + aoff + mt * (16 * RST * 4) + kk * 32);
            if (RND_A) {
#pragma unroll
                for (int mt = 0; mt < 2; mt++)
#pragma unroll
                    for (int r = 0; r < 4; r++) af[mt][r] = rna_tf32_u(af[mt][r]);
            }
#pragma unroll
            for (int ntp = 0; ntp < 4; ntp++)
                ldsm4(bf[ntp], sbB + boff + ntp * (16 * RST * 4) + kk * 32);
            if (RND_B) {
#pragma unroll
                for (int ntp = 0; ntp < 4; ntp++)
#pragma unroll
                    for (int r = 0; r < 4; r++) bf[ntp][r] = rna_tf32_u(bf[ntp][r]);
            }
#pragma unroll
            for (int mt = 0; mt < 2; mt++)
#pragma unroll
                for (int nt = 0; nt < 8; nt++)
                    mma_tf32(acc[mt][nt], af[mt], bf[nt >> 1] + (nt & 1) * 2);
        }
    }

    // Epilogue
    const bool doTrans = TRANSC && (z == zTrans);
#pragma unroll
    for (int mt = 0; mt < 2; mt++) {
        const int r = m0 + wm * 32 + mt * 16 + grp;
#pragma unroll
        for (int nt = 0; nt < 8; nt++) {
            const int c = n0 + wn * 64 + nt * 8 + q * 2;
            float2 v0, v1;
            v0.x = acc[mt][nt][0] * alpha;
            v0.y = acc[mt][nt][1] * alpha;
            v1.x = acc[mt][nt][2] * alpha;
            v1.y = acc[mt][nt][3] * alpha;
            if (BIAS) {
                const float2 bb = *(const float2*)(biasb + c);
                v0.x += bb.x; v0.y += bb.y;
                v1.x += bb.x; v1.y += bb.y;
            }
            if (ROUND) {
                v0.x = rna_tf32(v0.x); v0.y = rna_tf32(v0.y);
                v1.x = rna_tf32(v1.x); v1.y = rna_tf32(v1.y);
            }
            if (doTrans) {
                // rows r, r+8 are (batch b, seq l); write Ct[b][c][l] (Ct: [D, LK] per batch)
                const int b0 = r >> 11,       l0 = r & 2047;
                const int b1 = (r + 8) >> 11, l1 = (r + 8) & 2047;
                float* t0 = Ct + (size_t)b0 * D_ * LK_ + l0;
                float* t1 = Ct + (size_t)b1 * D_ * LK_ + l1;
                t0[(size_t)(c)     * LK_] = v0.x;
                t0[(size_t)(c + 1) * LK_] = v0.y;
                t1[(size_t)(c)     * LK_] = v1.x;
                t1[(size_t)(c + 1) * LK_] = v1.y;
            } else {
                *(float2*)(Cb + (size_t)r * N + c)       = v0;
                *(float2*)(Cb + (size_t)(r + 8) * N + c) = v1;
            }
        }
    }
}

// ---------------- aux kernels ------------------------------------------------
// Wv [R,C] row-major -> out [C,R] row-major, tf32-rounded.
__global__ __launch_bounds__(256)
void transpose_round_k(const float* __restrict__ in, float* __restrict__ out,
                       int R, int C)
{
    __shared__ float t[32][33];
    const int c0 = blockIdx.x * 32, r0 = blockIdx.y * 32;
    const int tx = threadIdx.x & 31, ty = threadIdx.x >> 5;
#pragma unroll
    for (int i = 0; i < 32; i += 8)
        t[ty + i][tx] = in[(size_t)(r0 + ty + i) * C + c0 + tx];
    __syncthreads();
#pragma unroll
    for (int i = 0; i < 32; i += 8)
        out[(size_t)(c0 + ty + i) * R + r0 + tx] = rna_tf32(t[tx][ty + i]);
}

// g_bias: slot0 = zeros (Y path), slot1 = bv.
__global__ __launch_bounds__(256)
void bias2_k(const float* __restrict__ bv, float* __restrict__ out)
{
    const int i = blockIdx.x * 256 + threadIdx.x;
    if (i < D_)           out[i] = 0.f;
    else if (i < 2 * D_)  out[i] = bv[i - D_];
}

// w[d] = Wk[d,:] . bq   (one warp per row)
__global__ __launch_bounds__(256)
void matvec_w_k(const float* __restrict__ Wk, const float* __restrict__ bq,
                float* __restrict__ w)
{
    const int row  = blockIdx.x * 8 + (threadIdx.x >> 5);
    const int lane = threadIdx.x & 31;
    const float* p = Wk + (size_t)row * D_;
    float s = 0.f;
    for (int i = lane * 4; i < D_; i += 128) {
        const float4 a = *(const float4*)(p + i);
        const float4 b = *(const float4*)(bq + i);
        s += a.x * b.x + a.y * b.y + a.z * b.z + a.w * b.w;
    }
#pragma unroll
    for (int o = 16; o; o >>= 1) s += __shfl_xor_sync(0xFFFFFFFFu, s, o);
    if (lane == 0) w[row] = s;
}

// beta[row] = (Xk[row,:] . w) / 32   (one warp per row; row = b*LK + j)
__global__ __launch_bounds__(256)
void beta_k(const float* __restrict__ xk, const float* __restrict__ w,
            float* __restrict__ beta)
{
    const int row  = blockIdx.x * 8 + (threadIdx.x >> 5);
    const int lane = threadIdx.x & 31;
    const float* p = xk + (size_t)row * D_;
    float s = 0.f;
    for (int i = lane * 4; i < D_; i += 128) {
        const float4 a = *(const float4*)(p + i);
        const float4 b = *(const float4*)(w + i);
        s += a.x * b.x + a.y * b.y + a.z * b.z + a.w * b.w;
    }
#pragma unroll
    for (int o = 16; o; o >>= 1) s += __shfl_xor_sync(0xFFFFFFFFu, s, o);
    if (lane == 0) beta[row] = s * (1.f / 32.f);
}

// Row softmax over LK_ columns; tf32-rounded output.
__global__ __launch_bounds__(256)
void softmax_k(float* __restrict__ S)
{
    __shared__ float red[256];
    float* p = S + (size_t)blockIdx.x * LK_;
    const int tid = threadIdx.x;

    float v[8];
    *(float4*)(v)     = *(const float4*)(p + tid * 8);
    *(float4*)(v + 4) = *(const float4*)(p + tid * 8 + 4);

    float mx = v[0];
#pragma unroll
    for (int i = 1; i < 8; i++) mx = fmaxf(mx, v[i]);
    red[tid] = mx;
    __syncthreads();
    for (int s = 128; s > 0; s >>= 1) {
        if (tid < s) red[tid] = fmaxf(red[tid], red[tid + s]);
        __syncthreads();
    }
    mx = red[0];
    __syncthreads();

    float sum = 0.f;
#pragma unroll
    for (int i = 0; i < 8; i++) { v[i] = __expf(v[i] - mx); sum += v[i]; }
    red[tid] = sum;
    __syncthreads();
    for (int s = 128; s > 0; s >>= 1) {
        if (tid < s) red[tid] += red[tid + s];
        __syncthreads();
    }
    const float inv = 1.f / red[0];
    __syncthreads();

#pragma unroll
    for (int i = 0; i < 8; i++) v[i] = rna_tf32(v[i] * inv);
    *(float4*)(p + tid * 8)     = *(float4*)(v);
    *(float4*)(p + tid * 8 + 4) = *(float4*)(v + 4);
}

// ---------------- host -------------------------------------------------------
extern "C" void kernel_launch(void* const* d_in, const int* in_sizes, int n_in,
                              void* d_out, int out_size)
{
    const float* q_in = (const float*)d_in[0];
    const float* k_in = (const float*)d_in[1];
    const float* v_in = (const float*)d_in[2];
    const float* Wq   = (const float*)d_in[3];
    const float* bq   = (const float*)d_in[4];
    const float* Wk   = (const float*)d_in[5];
    // bk (d_in[6]) cancels in row-softmax; unused.
    const float* Wv   = (const float*)d_in[7];
    const float* bv   = (const float*)d_in[8];
    float* out = (float*)d_out;

    float *pwt, *pbias, *py, *pvt, *ps, *pw, *pbeta;
    cudaGetSymbolAddress((void**)&pwt,   g_wt);
    cudaGetSymbolAddress((void**)&pbias, g_bias);
    cudaGetSymbolAddress((void**)&py,    g_y);
    cudaGetSymbolAddress((void**)&pvt,   g_vt);
    cudaGetSymbolAddress((void**)&ps,    g_s);
    cudaGetSymbolAddress((void**)&pw,    g_w);
    cudaGetSymbolAddress((void**)&pbeta, g_beta);

    cudaFuncSetAttribute((const void*)gemm_tf32<false, true,  true,  false, true,  false>,
                         cudaFuncAttributeMaxDynamicSharedMemorySize, GEMM_SMEM);
    cudaFuncSetAttribute((const void*)gemm_tf32<true,  true,  false, true,  true,  true >,
                         cudaFuncAttributeMaxDynamicSharedMemorySize, GEMM_SMEM);
    cudaFuncSetAttribute((const void*)gemm_tf32<false, false, true,  true,  false, false>,
                         cudaFuncAttributeMaxDynamicSharedMemorySize, GEMM_SMEM);
    cudaFuncSetAttribute((const void*)gemm_tf32<false, false, false, false, false, false>,
                         cudaFuncAttributeMaxDynamicSharedMemorySize, GEMM_SMEM);

    const size_t T = (size_t)B_ * LQ_ * D_;

    // 1) Mt = Wk @ Wq^T (rounded) -> g_wt slot0 ; Wv^T (rounded) -> slot1 ; biases; w; beta
    gemm_tf32<false, true, true, false, true, false><<<dim3(D_ / BN, D_ / BM, 1), 256, GEMM_SMEM>>>(
        Wk, nullptr, Wq, nullptr, pwt, nullptr, -1, D_, D_, 1.f, 0, 0, 0, 0);
    transpose_round_k<<<dim3(D_ / 32, D_ / 32), 256>>>(Wv, pwt + (size_t)D_ * D_, D_, D_);
    bias2_k<<<(2 * D_ + 255) / 256, 256>>>(bv, pbias);
    matvec_w_k<<<D_ / 8, 256>>>(Wk, bq, pw);
    beta_k<<<(B_ * LK_) / 8, 256>>>(k_in, pw, pbeta);

    // 2) projections: z=0: Y = rna(Xq) @ M -> g_y ; z=1: V = rna(Xv) @ Wv^T + bv -> g_vt (transposed)
    gemm_tf32<true, true, false, true, true, true><<<dim3(D_ / BN, (B_ * LQ_) / BM, 2), 256, GEMM_SMEM>>>(
        q_in, v_in, pwt, pbias, py, pvt, /*zTrans=*/1, D_, D_, 1.f,
        0, (size_t)D_ * D_, T, D_);

    // 3) scores S = (Y @ Xk^T)/32 + beta  (Xk rounded in-fragment; beta pre-divided by 32)
    gemm_tf32<false, false, true, true, false, false><<<dim3(LK_ / BN, LQ_ / BM, B_), 256, GEMM_SMEM>>>(
        py, nullptr, k_in, pbeta, ps, nullptr, -1,
        LK_, D_, 1.f / 32.f,
        (size_t)LQ_ * D_, (size_t)LK_ * D_, (size_t)LQ_ * LK_, LK_);

    // 4) softmax rows (tf32-rounded probs)
    softmax_k<<<B_ * LQ_, 256>>>(ps);

    // 5) O = P @ V  (V^T is [D, LK] K-major)
    gemm_tf32<false, false, false, false, false, false><<<dim3(D_ / BN, LQ_ / BM, B_), 256, GEMM_SMEM>>>(
        ps, nullptr, pvt, nullptr, out, nullptr, -1,
        D_, LK_, 1.f,
        (size_t)LQ_ * LK_, (size_t)D_ * LK_, (size_t)LQ_ * D_, 0);
}

// round 11
// speedup vs baseline: 1.2389x; 1.0400x over previous
#include <cuda_runtime.h>
#include <cstdint>

#define B_  4
#define LQ_ 2048
#define LK_ 2048
#define D_  1024

// ---------------- scratch (static device globals; no runtime alloc) ----------
__device__ float g_wt  [(size_t)2 * D_ * D_];        // slot0: Mt=Wk@Wq^T ; slot1: Wv^T
__device__ float g_bias[2 * D_];                     // slot0: zeros ; slot1: bv
__device__ float g_y   [(size_t)B_ * LQ_ * D_];      // Y = Xq @ M (tf32-rounded)
__device__ float g_kr  [(size_t)B_ * LK_ * D_];      // tf32-rounded k_in
__device__ float g_vt  [(size_t)B_ * D_ * LK_];      // V^T per batch (tf32-rounded)
__device__ float g_s   [(size_t)B_ * LQ_ * LK_];     // scores / probs
__device__ float g_w   [D_];                         // w = Wk @ bq
__device__ float g_beta[(size_t)B_ * LK_];           // beta_j / 32 per key position

// ---------------- PTX helpers ------------------------------------------------
__device__ __forceinline__ uint32_t smem_u32(const void* p) {
    uint32_t a;
    asm("{ .reg .u64 t; cvta.to.shared.u64 t, %1; cvt.u32.u64 %0, t; }" : "=r"(a) : "l"(p));
    return a;
}
__device__ __forceinline__ float rna_tf32(float x) {
    uint32_t r; asm("cvt.rna.tf32.f32 %0, %1;" : "=r"(r) : "f"(x));
    return __uint_as_float(r);
}
__device__ __forceinline__ uint32_t rna_tf32_u(uint32_t x) {
    uint32_t r; asm("cvt.rna.tf32.f32 %0, %1;" : "=r"(r) : "f"(__uint_as_float(x)));
    return r;
}
__device__ __forceinline__ void cp16(uint32_t s, const void* g) {
    asm volatile("cp.async.cg.shared.global [%0], [%1], 16;" :: "r"(s), "l"(g));
}
#define CP_COMMIT() asm volatile("cp.async.commit_group;" ::: "memory")
#define CP_WAIT(n)  asm volatile("cp.async.wait_group %0;" :: "n"(n) : "memory")

__device__ __forceinline__ void ldsm4(uint32_t* r, uint32_t addr) {
    asm volatile("ldmatrix.sync.aligned.m8n8.x4.shared.b16 {%0,%1,%2,%3}, [%4];"
        : "=r"(r[0]), "=r"(r[1]), "=r"(r[2]), "=r"(r[3]) : "r"(addr));
}

__device__ __forceinline__ void mma_tf32(float* c, const uint32_t* a, const uint32_t* b) {
    asm volatile(
        "mma.sync.aligned.m16n8k8.row.col.f32.tf32.tf32.f32 "
        "{%0,%1,%2,%3}, {%4,%5,%6,%7}, {%8,%9}, {%0,%1,%2,%3};"
        : "+f"(c[0]), "+f"(c[1]), "+f"(c[2]), "+f"(c[3])
        : "r"(a[0]), "r"(a[1]), "r"(a[2]), "r"(a[3]), "r"(b[0]), "r"(b[1]));
}

// ---------------- tf32 mma.sync NT GEMM --------------------------------------
// C[M,N] = alpha * A[M,K] @ Bt[N,K]^T (+ bias), batched via blockIdx.z.
// Block tile 128x128x32; 256 threads = 8 warps in 4(M) x 2(N); warp tile 32x64.
// 128 regs/thread -> 2 CTAs/SM -> 16 warps/SM = 4 per SMSP.
// RND_A/RND_B: rna-round A/B fragments in-register (for raw fp32 operands).
// TRANSC: for z==zTrans, epilogue writes C transposed into Ct ([D, LK] per batch).
#define BM 128
#define BN 128
#define BK 32
#define RST 36
#define STAGE_FLOATS ((BM + BN) * RST)   // 9216 floats = 36864 B
#define STAGES 3
#define GEMM_SMEM (STAGES * STAGE_FLOATS * 4)

template <bool MULTI_A, bool RND_A, bool RND_B, bool BIAS, bool ROUND, bool TRANSC>
__global__ __launch_bounds__(256, 2)
void gemm_tf32(const float* __restrict__ A0, const float* __restrict__ A1,
               const float* __restrict__ Bt,
               const float* __restrict__ bias, float* __restrict__ C,
               float* __restrict__ Ct, int zTrans,
               int N, int K, float alpha,
               size_t sA, size_t sB, size_t sC, int sBias)
{
    extern __shared__ float smf[];
    const uint32_t sb32 = smem_u32(smf);

    const int tid  = threadIdx.x;
    const int wid  = tid >> 5;
    const int lane = tid & 31;
    const int grp  = lane >> 2;   // 0..7
    const int q    = lane & 3;    // 0..3
    const int wm   = wid & 3;     // 4 warps along M -> 32 rows each
    const int wn   = wid >> 2;    // 2 warps along N -> 64 cols each

    const int m0 = blockIdx.y * BM;
    const int n0 = blockIdx.x * BN;
    const int z  = blockIdx.z;

    const float* Ab = MULTI_A ? (z == 0 ? A0 : A1) : A0 + (size_t)z * sA;
    const float* Bb = Bt + (size_t)z * sB;
    const float* biasb = BIAS ? (bias + (size_t)z * sBias) : nullptr;
    float* Cb = C + (size_t)z * sC;

    const int KT = K / BK;

    // per-lane ldmatrix byte offsets
    const uint32_t aoff =
        ((wm * 32 + (lane & 7) + ((lane >> 3) & 1) * 8) * RST + ((lane >> 4) & 1) * 4) * 4;
    const uint32_t boff =
        ((wn * 64 + (lane & 7) + ((lane >> 4) & 1) * 8) * RST + ((lane >> 3) & 1) * 4) * 4;

    // async load of one stage: A 128x32 + B 128x32, K-major rows (8 x 16B segs)
    auto load_stage = [&](int s, int kt) {
        const uint32_t abase = sb32 + s * STAGE_FLOATS * 4;
        const uint32_t bbase = abase + BM * RST * 4;
        const int k0 = kt * BK;
#pragma unroll
        for (int j = 0; j < 4; j++) {
            const int idx = tid + j * 256;          // 0..1023
            const int row = idx >> 3, seg = idx & 7;
            cp16(abase + (row * RST + seg * 4) * 4,
                 Ab + (size_t)(m0 + row) * K + k0 + seg * 4);
        }
#pragma unroll
        for (int j = 0; j < 4; j++) {
            const int idx = tid + j * 256;
            const int row = idx >> 3, seg = idx & 7;
            cp16(bbase + (row * RST + seg * 4) * 4,
                 Bb + (size_t)(n0 + row) * K + k0 + seg * 4);
        }
        CP_COMMIT();
    };

    float acc[2][8][4];
#pragma unroll
    for (int i = 0; i < 2; i++)
#pragma unroll
        for (int j = 0; j < 8; j++)
#pragma unroll
            for (int r = 0; r < 4; r++) acc[i][j][r] = 0.f;

    load_stage(0, 0);
    load_stage(1, 1);

    for (int kt = 0; kt < KT; kt++) {
        const int s = kt % STAGES;
        if (kt < KT - 1) { CP_WAIT(1); } else { CP_WAIT(0); }
        __syncthreads();

        if (kt + 2 < KT) load_stage((kt + 2) % STAGES, kt + 2);

        const uint32_t sa = sb32 + s * STAGE_FLOATS * 4;
        const uint32_t sbB = sa + BM * RST * 4;

#pragma unroll
        for (int kk = 0; kk < 4; kk++) {
            uint32_t af[2][4], bf[4][4];
#pragma unroll
            for (int mt = 0; mt < 2; mt++)
                ldsm4(af[mt], sa + aoff + mt * (16 * RST * 4) + kk * 32);
            if (RND_A) {
#pragma unroll
                for (int mt = 0; mt < 2; mt++)
#pragma unroll
                    for (int r = 0; r < 4; r++) af[mt][r] = rna_tf32_u(af[mt][r]);
            }
#pragma unroll
            for (int ntp = 0; ntp < 4; ntp++)
                ldsm4(bf[ntp], sbB + boff + ntp * (16 * RST * 4) + kk * 32);
            if (RND_B) {
#pragma unroll
                for (int ntp = 0; ntp < 4; ntp++)
#pragma unroll
                    for (int r = 0; r < 4; r++) bf[ntp][r] = rna_tf32_u(bf[ntp][r]);
            }
#pragma unroll
            for (int mt = 0; mt < 2; mt++)
#pragma unroll
                for (int nt = 0; nt < 8; nt++)
                    mma_tf32(acc[mt][nt], af[mt], bf[nt >> 1] + (nt & 1) * 2);
        }
    }

    // Epilogue
    const bool doTrans = TRANSC && (z == zTrans);
#pragma unroll
    for (int mt = 0; mt < 2; mt++) {
        const int r = m0 + wm * 32 + mt * 16 + grp;
#pragma unroll
        for (int nt = 0; nt < 8; nt++) {
            const int c = n0 + wn * 64 + nt * 8 + q * 2;
            float2 v0, v1;
            v0.x = acc[mt][nt][0] * alpha;
            v0.y = acc[mt][nt][1] * alpha;
            v1.x = acc[mt][nt][2] * alpha;
            v1.y = acc[mt][nt][3] * alpha;
            if (BIAS) {
                const float2 bb = *(const float2*)(biasb + c);
                v0.x += bb.x; v0.y += bb.y;
                v1.x += bb.x; v1.y += bb.y;
            }
            if (ROUND) {
                v0.x = rna_tf32(v0.x); v0.y = rna_tf32(v0.y);
                v1.x = rna_tf32(v1.x); v1.y = rna_tf32(v1.y);
            }
            if (doTrans) {
                // rows r, r+8 are (batch b, seq l); write Ct[b][c][l] (Ct: [D, LK] per batch)
                const int b0 = r >> 11,       l0 = r & 2047;
                const int b1 = (r + 8) >> 11, l1 = (r + 8) & 2047;
                float* t0 = Ct + (size_t)b0 * D_ * LK_ + l0;
                float* t1 = Ct + (size_t)b1 * D_ * LK_ + l1;
                t0[(size_t)(c)     * LK_] = v0.x;
                t0[(size_t)(c + 1) * LK_] = v0.y;
                t1[(size_t)(c)     * LK_] = v1.x;
                t1[(size_t)(c + 1) * LK_] = v1.y;
            } else {
                *(float2*)(Cb + (size_t)r * N + c)       = v0;
                *(float2*)(Cb + (size_t)(r + 8) * N + c) = v1;
            }
        }
    }
}

// ---------------- aux kernels ------------------------------------------------
// Wv [R,C] row-major -> out [C,R] row-major, tf32-rounded.
__global__ __launch_bounds__(256)
void transpose_round_k(const float* __restrict__ in, float* __restrict__ out,
                       int R, int C)
{
    __shared__ float t[32][33];
    const int c0 = blockIdx.x * 32, r0 = blockIdx.y * 32;
    const int tx = threadIdx.x & 31, ty = threadIdx.x >> 5;
#pragma unroll
    for (int i = 0; i < 32; i += 8)
        t[ty + i][tx] = in[(size_t)(r0 + ty + i) * C + c0 + tx];
    __syncthreads();
#pragma unroll
    for (int i = 0; i < 32; i += 8)
        out[(size_t)(c0 + ty + i) * R + r0 + tx] = rna_tf32(t[tx][ty + i]);
}

// g_bias: slot0 = zeros (Y path), slot1 = bv.
__global__ __launch_bounds__(256)
void bias2_k(const float* __restrict__ bv, float* __restrict__ out)
{
    const int i = blockIdx.x * 256 + threadIdx.x;
    if (i < D_)           out[i] = 0.f;
    else if (i < 2 * D_)  out[i] = bv[i - D_];
}

// w[d] = Wk[d,:] . bq   (4 warps per row, smem-combined)
__global__ __launch_bounds__(256)
void matvec_w_k(const float* __restrict__ Wk, const float* __restrict__ bq,
                float* __restrict__ w)
{
    __shared__ float part[2][4];
    const int sub  = threadIdx.x >> 7;           // 0..1 rows per block
    const int t    = threadIdx.x & 127;          // 128 threads per row
    const int row  = blockIdx.x * 2 + sub;
    const float* p = Wk + (size_t)row * D_;
    float s = 0.f;
    for (int i = t * 4; i < D_; i += 512) {
        const float4 a = *(const float4*)(p + i);
        const float4 b = *(const float4*)(bq + i);
        s += a.x * b.x + a.y * b.y + a.z * b.z + a.w * b.w;
    }
#pragma unroll
    for (int o = 16; o; o >>= 1) s += __shfl_xor_sync(0xFFFFFFFFu, s, o);
    if ((t & 31) == 0) part[sub][t >> 5] = s;
    __syncthreads();
    if (t == 0) w[row] = part[sub][0] + part[sub][1] + part[sub][2] + part[sub][3];
}

// beta[row] = (Xk[row,:] . w) / 32 ; also writes tf32-rounded Xk into kr.
__global__ __launch_bounds__(256)
void beta_k(const float* __restrict__ xk, const float* __restrict__ w,
            float* __restrict__ beta, float* __restrict__ kr)
{
    const int row  = blockIdx.x * 8 + (threadIdx.x >> 5);
    const int lane = threadIdx.x & 31;
    const float* p = xk + (size_t)row * D_;
    float*       o = kr + (size_t)row * D_;
    float s = 0.f;
    for (int i = lane * 4; i < D_; i += 128) {
        float4 a = *(const float4*)(p + i);
        const float4 b = *(const float4*)(w + i);
        s += a.x * b.x + a.y * b.y + a.z * b.z + a.w * b.w;
        a.x = rna_tf32(a.x); a.y = rna_tf32(a.y);
        a.z = rna_tf32(a.z); a.w = rna_tf32(a.w);
        *(float4*)(o + i) = a;
    }
#pragma unroll
    for (int of = 16; of; of >>= 1) s += __shfl_xor_sync(0xFFFFFFFFu, s, of);
    if (lane == 0) beta[row] = s * (1.f / 32.f);
}

// Row softmax over LK_ columns; tf32-rounded output.
__global__ __launch_bounds__(256)
void softmax_k(float* __restrict__ S)
{
    __shared__ float red[256];
    float* p = S + (size_t)blockIdx.x * LK_;
    const int tid = threadIdx.x;

    float v[8];
    *(float4*)(v)     = *(const float4*)(p + tid * 8);
    *(float4*)(v + 4) = *(const float4*)(p + tid * 8 + 4);

    float mx = v[0];
#pragma unroll
    for (int i = 1; i < 8; i++) mx = fmaxf(mx, v[i]);
    red[tid] = mx;
    __syncthreads();
    for (int s = 128; s > 0; s >>= 1) {
        if (tid < s) red[tid] = fmaxf(red[tid], red[tid + s]);
        __syncthreads();
    }
    mx = red[0];
    __syncthreads();

    float sum = 0.f;
#pragma unroll
    for (int i = 0; i < 8; i++) { v[i] = __expf(v[i] - mx); sum += v[i]; }
    red[tid] = sum;
    __syncthreads();
    for (int s = 128; s > 0; s >>= 1) {
        if (tid < s) red[tid] += red[tid + s];
        __syncthreads();
    }
    const float inv = 1.f / red[0];
    __syncthreads();

#pragma unroll
    for (int i = 0; i < 8; i++) v[i] = rna_tf32(v[i] * inv);
    *(float4*)(p + tid * 8)     = *(float4*)(v);
    *(float4*)(p + tid * 8 + 4) = *(float4*)(v + 4);
}

// ---------------- host -------------------------------------------------------
extern "C" void kernel_launch(void* const* d_in, const int* in_sizes, int n_in,
                              void* d_out, int out_size)
{
    const float* q_in = (const float*)d_in[0];
    const float* k_in = (const float*)d_in[1];
    const float* v_in = (const float*)d_in[2];
    const float* Wq   = (const float*)d_in[3];
    const float* bq   = (const float*)d_in[4];
    const float* Wk   = (const float*)d_in[5];
    // bk (d_in[6]) cancels in row-softmax; unused.
    const float* Wv   = (const float*)d_in[7];
    const float* bv   = (const float*)d_in[8];
    float* out = (float*)d_out;

    float *pwt, *pbias, *py, *pkr, *pvt, *ps, *pw, *pbeta;
    cudaGetSymbolAddress((void**)&pwt,   g_wt);
    cudaGetSymbolAddress((void**)&pbias, g_bias);
    cudaGetSymbolAddress((void**)&py,    g_y);
    cudaGetSymbolAddress((void**)&pkr,   g_kr);
    cudaGetSymbolAddress((void**)&pvt,   g_vt);
    cudaGetSymbolAddress((void**)&ps,    g_s);
    cudaGetSymbolAddress((void**)&pw,    g_w);
    cudaGetSymbolAddress((void**)&pbeta, g_beta);

    cudaFuncSetAttribute((const void*)gemm_tf32<false, true,  true,  false, true,  false>,
                         cudaFuncAttributeMaxDynamicSharedMemorySize, GEMM_SMEM);
    cudaFuncSetAttribute((const void*)gemm_tf32<true,  true,  false, true,  true,  true >,
                         cudaFuncAttributeMaxDynamicSharedMemorySize, GEMM_SMEM);
    cudaFuncSetAttribute((const void*)gemm_tf32<false, false, false, true,  false, false>,
                         cudaFuncAttributeMaxDynamicSharedMemorySize, GEMM_SMEM);
    cudaFuncSetAttribute((const void*)gemm_tf32<false, false, false, false, false, false>,
                         cudaFuncAttributeMaxDynamicSharedMemorySize, GEMM_SMEM);

    const size_t T = (size_t)B_ * LQ_ * D_;

    // 1) prep: Mt = Wk @ Wq^T -> g_wt slot0 ; Wv^T -> slot1 ; biases ; w ; beta + rounded k
    gemm_tf32<false, true, true, false, true, false><<<dim3(D_ / BN, D_ / BM, 1), 256, GEMM_SMEM>>>(
        Wk, nullptr, Wq, nullptr, pwt, nullptr, -1, D_, D_, 1.f, 0, 0, 0, 0);
    transpose_round_k<<<dim3(D_ / 32, D_ / 32), 256>>>(Wv, pwt + (size_t)D_ * D_, D_, D_);
    bias2_k<<<(2 * D_ + 255) / 256, 256>>>(bv, pbias);
    matvec_w_k<<<D_ / 2, 256>>>(Wk, bq, pw);
    beta_k<<<(B_ * LK_) / 8, 256>>>(k_in, pw, pbeta, pkr);

    // 2) projections: z=0: Y = rna(Xq) @ M -> g_y ; z=1: V = rna(Xv) @ Wv^T + bv -> g_vt (transposed)
    gemm_tf32<true, true, false, true, true, true><<<dim3(D_ / BN, (B_ * LQ_) / BM, 2), 256, GEMM_SMEM>>>(
        q_in, v_in, pwt, pbias, py, pvt, /*zTrans=*/1, D_, D_, 1.f,
        0, (size_t)D_ * D_, T, D_);

    // 3) scores S = (Y @ Kr^T)/32 + beta  (operands pre-rounded; no in-loop cvt)
    gemm_tf32<false, false, false, true, false, false><<<dim3(LK_ / BN, LQ_ / BM, B_), 256, GEMM_SMEM>>>(
        py, nullptr, pkr, pbeta, ps, nullptr, -1,
        LK_, D_, 1.f / 32.f,
        (size_t)LQ_ * D_, (size_t)LK_ * D_, (size_t)LQ_ * LK_, LK_);

    // 4) softmax rows (tf32-rounded probs)
    softmax_k<<<B_ * LQ_, 256>>>(ps);

    // 5) O = P @ V  (V^T is [D, LK] K-major)
    gemm_tf32<false, false, false, false, false, false><<<dim3(D_ / BN, LQ_ / BM, B_), 256, GEMM_SMEM>>>(
        ps, nullptr, pvt, nullptr, out, nullptr, -1,
        D_, LK_, 1.f,
        (size_t)LQ_ * LK_, (size_t)D_ * LK_, (size_t)LQ_ * D_, 0);
}

// round 13
// speedup vs baseline: 1.2915x; 1.0424x over previous
#include <cuda_runtime.h>
#include <cstdint>

#define B_  4
#define LQ_ 2048
#define LK_ 2048
#define D_  1024

// ---------------- scratch (static device globals; no runtime alloc) ----------
__device__ float g_wt  [(size_t)2 * D_ * D_];        // slot0: Mt=Wk@Wq^T ; slot1: Wv^T
__device__ float g_bias[2 * D_];                     // slot0: zeros ; slot1: bv
__device__ float g_y   [(size_t)B_ * LQ_ * D_];      // scratch Wq rounded / Y = Xq @ M
__device__ float g_kr  [(size_t)B_ * LK_ * D_];      // tf32-rounded k_in
__device__ float g_vt  [(size_t)B_ * D_ * LK_];      // V^T per batch (tf32-rounded)
__device__ float g_s   [(size_t)B_ * LQ_ * LK_];     // unnormalized exp scores
__device__ float g_w   [D_];                         // w = Wk @ bq
__device__ float g_beta[(size_t)B_ * LK_];           // beta_j / 32 per key position
__device__ float g_rsum[(size_t)B_ * LQ_];           // row sums of exp scores

// ---------------- PTX helpers ------------------------------------------------
__device__ __forceinline__ uint32_t smem_u32(const void* p) {
    uint32_t a;
    asm("{ .reg .u64 t; cvta.to.shared.u64 t, %1; cvt.u32.u64 %0, t; }" : "=r"(a) : "l"(p));
    return a;
}
__device__ __forceinline__ float rna_tf32(float x) {
    uint32_t r; asm("cvt.rna.tf32.f32 %0, %1;" : "=r"(r) : "f"(x));
    return __uint_as_float(r);
}
__device__ __forceinline__ uint32_t rna_tf32_u(uint32_t x) {
    uint32_t r; asm("cvt.rna.tf32.f32 %0, %1;" : "=r"(r) : "f"(__uint_as_float(x)));
    return r;
}
__device__ __forceinline__ void cp16(uint32_t s, const void* g) {
    asm volatile("cp.async.cg.shared.global [%0], [%1], 16;" :: "r"(s), "l"(g));
}
#define CP_COMMIT() asm volatile("cp.async.commit_group;" ::: "memory")
#define CP_WAIT(n)  asm volatile("cp.async.wait_group %0;" :: "n"(n) : "memory")

__device__ __forceinline__ void ldsm4(uint32_t* r, uint32_t addr) {
    asm volatile("ldmatrix.sync.aligned.m8n8.x4.shared.b16 {%0,%1,%2,%3}, [%4];"
        : "=r"(r[0]), "=r"(r[1]), "=r"(r[2]), "=r"(r[3]) : "r"(addr));
}

__device__ __forceinline__ void mma_tf32(float* c, const uint32_t* a, const uint32_t* b) {
    asm volatile(
        "mma.sync.aligned.m16n8k8.row.col.f32.tf32.tf32.f32 "
        "{%0,%1,%2,%3}, {%4,%5,%6,%7}, {%8,%9}, {%0,%1,%2,%3};"
        : "+f"(c[0]), "+f"(c[1]), "+f"(c[2]), "+f"(c[3])
        : "r"(a[0]), "r"(a[1]), "r"(a[2]), "r"(a[3]), "r"(b[0]), "r"(b[1]));
}

// ---------------- tf32 mma.sync NT GEMM --------------------------------------
// C[M,N] = alpha * A[M,K] @ Bt[N,K]^T (+ bias), batched via blockIdx.z.
// Block tile 128x128x32; 256 threads = 8 warps in 4(M) x 2(N); warp tile 32x64.
// EXP: epilogue applies expf and atomically accumulates row sums into rsum.
// SCALE: epilogue multiplies rows by 1/rsum[row] (PV normalization).
// TRANSC: for z==zTrans, epilogue writes C transposed into Ct ([D, LK] per batch).
#define BM 128
#define BN 128
#define BK 32
#define RST 36
#define STAGE_FLOATS ((BM + BN) * RST)   // 9216 floats = 36864 B
#define STAGES 3
#define GEMM_SMEM (STAGES * STAGE_FLOATS * 4)

template <bool MULTI_A, bool RND_A, bool BIAS, bool ROUND, bool TRANSC, bool EXP, bool SCALE>
__global__ __launch_bounds__(256, 2)
void gemm_tf32(const float* __restrict__ A0, const float* __restrict__ A1,
               const float* __restrict__ Bt,
               const float* __restrict__ bias, float* __restrict__ C,
               float* __restrict__ Ct, int zTrans, float* __restrict__ rsum,
               int N, int K, float alpha,
               size_t sA, size_t sB, size_t sC, int sBias)
{
    extern __shared__ float smf[];
    const uint32_t sb32 = smem_u32(smf);

    const int tid  = threadIdx.x;
    const int wid  = tid >> 5;
    const int lane = tid & 31;
    const int grp  = lane >> 2;   // 0..7
    const int q    = lane & 3;    // 0..3
    const int wm   = wid & 3;     // 4 warps along M -> 32 rows each
    const int wn   = wid >> 2;    // 2 warps along N -> 64 cols each

    const int m0 = blockIdx.y * BM;
    const int n0 = blockIdx.x * BN;
    const int z  = blockIdx.z;

    const float* Ab = MULTI_A ? (z == 0 ? A0 : A1) : A0 + (size_t)z * sA;
    const float* Bb = Bt + (size_t)z * sB;
    const float* biasb = BIAS ? (bias + (size_t)z * sBias) : nullptr;
    float* Cb = C + (size_t)z * sC;

    const int KT = K / BK;

    // per-lane ldmatrix byte offsets
    const uint32_t aoff =
        ((wm * 32 + (lane & 7) + ((lane >> 3) & 1) * 8) * RST + ((lane >> 4) & 1) * 4) * 4;
    const uint32_t boff =
        ((wn * 64 + (lane & 7) + ((lane >> 4) & 1) * 8) * RST + ((lane >> 3) & 1) * 4) * 4;

    // async load of one stage: A 128x32 + B 128x32, K-major rows (8 x 16B segs)
    auto load_stage = [&](int s, int kt) {
        const uint32_t abase = sb32 + s * STAGE_FLOATS * 4;
        const uint32_t bbase = abase + BM * RST * 4;
        const int k0 = kt * BK;
#pragma unroll
        for (int j = 0; j < 4; j++) {
            const int idx = tid + j * 256;          // 0..1023
            const int row = idx >> 3, seg = idx & 7;
            cp16(abase + (row * RST + seg * 4) * 4,
                 Ab + (size_t)(m0 + row) * K + k0 + seg * 4);
        }
#pragma unroll
        for (int j = 0; j < 4; j++) {
            const int idx = tid + j * 256;
            const int row = idx >> 3, seg = idx & 7;
            cp16(bbase + (row * RST + seg * 4) * 4,
                 Bb + (size_t)(n0 + row) * K + k0 + seg * 4);
        }
        CP_COMMIT();
    };

    float acc[2][8][4];
#pragma unroll
    for (int i = 0; i < 2; i++)
#pragma unroll
        for (int j = 0; j < 8; j++)
#pragma unroll
            for (int r = 0; r < 4; r++) acc[i][j][r] = 0.f;

    load_stage(0, 0);
    load_stage(1, 1);

    for (int kt = 0; kt < KT; kt++) {
        const int s = kt % STAGES;
        if (kt < KT - 1) { CP_WAIT(1); } else { CP_WAIT(0); }
        __syncthreads();

        if (kt + 2 < KT) load_stage((kt + 2) % STAGES, kt + 2);

        const uint32_t sa = sb32 + s * STAGE_FLOATS * 4;
        const uint32_t sbB = sa + BM * RST * 4;

#pragma unroll
        for (int kk = 0; kk < 4; kk++) {
            uint32_t af[2][4], bf[4][4];
#pragma unroll
            for (int mt = 0; mt < 2; mt++)
                ldsm4(af[mt], sa + aoff + mt * (16 * RST * 4) + kk * 32);
            if (RND_A) {
#pragma unroll
                for (int mt = 0; mt < 2; mt++)
#pragma unroll
                    for (int r = 0; r < 4; r++) af[mt][r] = rna_tf32_u(af[mt][r]);
            }
#pragma unroll
            for (int ntp = 0; ntp < 4; ntp++)
                ldsm4(bf[ntp], sbB + boff + ntp * (16 * RST * 4) + kk * 32);
#pragma unroll
            for (int mt = 0; mt < 2; mt++)
#pragma unroll
                for (int nt = 0; nt < 8; nt++)
                    mma_tf32(acc[mt][nt], af[mt], bf[nt >> 1] + (nt & 1) * 2);
        }
    }

    // Epilogue
    const bool doTrans = TRANSC && (z == zTrans);
#pragma unroll
    for (int mt = 0; mt < 2; mt++) {
        const int r = m0 + wm * 32 + mt * 16 + grp;
        float rs0 = 0.f, rs1 = 0.f;     // EXP: row-sum partials
        float inv0 = 1.f, inv1 = 1.f;   // SCALE: row normalizers
        if (SCALE) {
            inv0 = 1.f / rsum[(size_t)z * LQ_ + r];
            inv1 = 1.f / rsum[(size_t)z * LQ_ + r + 8];
        }
#pragma unroll
        for (int nt = 0; nt < 8; nt++) {
            const int c = n0 + wn * 64 + nt * 8 + q * 2;
            float2 v0, v1;
            v0.x = acc[mt][nt][0] * alpha;
            v0.y = acc[mt][nt][1] * alpha;
            v1.x = acc[mt][nt][2] * alpha;
            v1.y = acc[mt][nt][3] * alpha;
            if (BIAS) {
                const float2 bb = *(const float2*)(biasb + c);
                v0.x += bb.x; v0.y += bb.y;
                v1.x += bb.x; v1.y += bb.y;
            }
            if (EXP) {
                v0.x = __expf(v0.x); v0.y = __expf(v0.y);
                v1.x = __expf(v1.x); v1.y = __expf(v1.y);
            }
            if (SCALE) {
                v0.x *= inv0; v0.y *= inv0;
                v1.x *= inv1; v1.y *= inv1;
            }
            if (ROUND) {
                v0.x = rna_tf32(v0.x); v0.y = rna_tf32(v0.y);
                v1.x = rna_tf32(v1.x); v1.y = rna_tf32(v1.y);
            }
            if (EXP) {
                rs0 += v0.x + v0.y;
                rs1 += v1.x + v1.y;
            }
            if (doTrans) {
                const int b0 = r >> 11,       l0 = r & 2047;
                const int b1 = (r + 8) >> 11, l1 = (r + 8) & 2047;
                float* t0 = Ct + (size_t)b0 * D_ * LK_ + l0;
                float* t1 = Ct + (size_t)b1 * D_ * LK_ + l1;
                t0[(size_t)(c)     * LK_] = v0.x;
                t0[(size_t)(c + 1) * LK_] = v0.y;
                t1[(size_t)(c)     * LK_] = v1.x;
                t1[(size_t)(c + 1) * LK_] = v1.y;
            } else {
                *(float2*)(Cb + (size_t)r * N + c)       = v0;
                *(float2*)(Cb + (size_t)(r + 8) * N + c) = v1;
            }
        }
        if (EXP) {
            rs0 += __shfl_xor_sync(0xFFFFFFFFu, rs0, 1);
            rs0 += __shfl_xor_sync(0xFFFFFFFFu, rs0, 2);
            rs1 += __shfl_xor_sync(0xFFFFFFFFu, rs1, 1);
            rs1 += __shfl_xor_sync(0xFFFFFFFFu, rs1, 2);
            if (q == 0) {
                atomicAdd(rsum + (size_t)z * LQ_ + r,     rs0);
                atomicAdd(rsum + (size_t)z * LQ_ + r + 8, rs1);
            }
        }
    }
}

// ---------------- aux kernels ------------------------------------------------
// Element-wise tf32 round copy (NO transpose).
__global__ __launch_bounds__(256)
void round_copy_k(const float* __restrict__ in, float* __restrict__ out, int n4)
{
    const int i = blockIdx.x * 256 + threadIdx.x;
    if (i < n4) {
        float4 v = ((const float4*)in)[i];
        v.x = rna_tf32(v.x); v.y = rna_tf32(v.y);
        v.z = rna_tf32(v.z); v.w = rna_tf32(v.w);
        ((float4*)out)[i] = v;
    }
}

// Wv [R,C] row-major -> out [C,R] row-major, tf32-rounded.
__global__ __launch_bounds__(256)
void transpose_round_k(const float* __restrict__ in, float* __restrict__ out,
                       int R, int C)
{
    __shared__ float t[32][33];
    const int c0 = blockIdx.x * 32, r0 = blockIdx.y * 32;
    const int tx = threadIdx.x & 31, ty = threadIdx.x >> 5;
#pragma unroll
    for (int i = 0; i < 32; i += 8)
        t[ty + i][tx] = in[(size_t)(r0 + ty + i) * C + c0 + tx];
    __syncthreads();
#pragma unroll
    for (int i = 0; i < 32; i += 8)
        out[(size_t)(c0 + ty + i) * R + r0 + tx] = rna_tf32(t[tx][ty + i]);
}

// g_bias: slot0 = zeros (Y path), slot1 = bv ; g_rsum zeroed.
__global__ __launch_bounds__(256)
void prep_small_k(const float* __restrict__ bv, float* __restrict__ bias_out,
                  float* __restrict__ rsum)
{
    const int i = blockIdx.x * 256 + threadIdx.x;
    if (i < D_)           bias_out[i] = 0.f;
    else if (i < 2 * D_)  bias_out[i] = bv[i - D_];
    if (i < B_ * LQ_)     rsum[i] = 0.f;
}

// w[d] = Wk[d,:] . bq   (4 warps per row, smem-combined)
__global__ __launch_bounds__(256)
void matvec_w_k(const float* __restrict__ Wk, const float* __restrict__ bq,
                float* __restrict__ w)
{
    __shared__ float part[2][4];
    const int sub  = threadIdx.x >> 7;
    const int t    = threadIdx.x & 127;
    const int row  = blockIdx.x * 2 + sub;
    const float* p = Wk + (size_t)row * D_;
    float s = 0.f;
    for (int i = t * 4; i < D_; i += 512) {
        const float4 a = *(const float4*)(p + i);
        const float4 b = *(const float4*)(bq + i);
        s += a.x * b.x + a.y * b.y + a.z * b.z + a.w * b.w;
    }
#pragma unroll
    for (int o = 16; o; o >>= 1) s += __shfl_xor_sync(0xFFFFFFFFu, s, o);
    if ((t & 31) == 0) part[sub][t >> 5] = s;
    __syncthreads();
    if (t == 0) w[row] = part[sub][0] + part[sub][1] + part[sub][2] + part[sub][3];
}

// beta[row] = (Xk[row,:] . w) / 32 ; also writes tf32-rounded Xk into kr.
__global__ __launch_bounds__(256)
void beta_k(const float* __restrict__ xk, const float* __restrict__ w,
            float* __restrict__ beta, float* __restrict__ kr)
{
    const int row  = blockIdx.x * 8 + (threadIdx.x >> 5);
    const int lane = threadIdx.x & 31;
    const float* p = xk + (size_t)row * D_;
    float*       o = kr + (size_t)row * D_;
    float s = 0.f;
    for (int i = lane * 4; i < D_; i += 128) {
        float4 a = *(const float4*)(p + i);
        const float4 b = *(const float4*)(w + i);
        s += a.x * b.x + a.y * b.y + a.z * b.z + a.w * b.w;
        a.x = rna_tf32(a.x); a.y = rna_tf32(a.y);
        a.z = rna_tf32(a.z); a.w = rna_tf32(a.w);
        *(float4*)(o + i) = a;
    }
#pragma unroll
    for (int of = 16; of; of >>= 1) s += __shfl_xor_sync(0xFFFFFFFFu, s, of);
    if (lane == 0) beta[row] = s * (1.f / 32.f);
}

// ---------------- host -------------------------------------------------------
extern "C" void kernel_launch(void* const* d_in, const int* in_sizes, int n_in,
                              void* d_out, int out_size)
{
    const float* q_in = (const float*)d_in[0];
    const float* k_in = (const float*)d_in[1];
    const float* v_in = (const float*)d_in[2];
    const float* Wq   = (const float*)d_in[3];
    const float* bq   = (const float*)d_in[4];
    const float* Wk   = (const float*)d_in[5];
    // bk (d_in[6]) cancels in row-softmax; unused.
    const float* Wv   = (const float*)d_in[7];
    const float* bv   = (const float*)d_in[8];
    float* out = (float*)d_out;

    float *pwt, *pbias, *py, *pkr, *pvt, *ps, *pw, *pbeta, *prs;
    cudaGetSymbolAddress((void**)&pwt,   g_wt);
    cudaGetSymbolAddress((void**)&pbias, g_bias);
    cudaGetSymbolAddress((void**)&py,    g_y);
    cudaGetSymbolAddress((void**)&pkr,   g_kr);
    cudaGetSymbolAddress((void**)&pvt,   g_vt);
    cudaGetSymbolAddress((void**)&ps,    g_s);
    cudaGetSymbolAddress((void**)&pw,    g_w);
    cudaGetSymbolAddress((void**)&pbeta, g_beta);
    cudaGetSymbolAddress((void**)&prs,   g_rsum);

    cudaFuncSetAttribute((const void*)gemm_tf32<false, true,  false, true,  false, false, false>,
                         cudaFuncAttributeMaxDynamicSharedMemorySize, GEMM_SMEM);
    cudaFuncSetAttribute((const void*)gemm_tf32<true,  true,  true,  true,  true,  false, false>,
                         cudaFuncAttributeMaxDynamicSharedMemorySize, GEMM_SMEM);
    cudaFuncSetAttribute((const void*)gemm_tf32<false, false, true,  true,  false, true,  false>,
                         cudaFuncAttributeMaxDynamicSharedMemorySize, GEMM_SMEM);
    cudaFuncSetAttribute((const void*)gemm_tf32<false, false, false, false, false, false, true >,
                         cudaFuncAttributeMaxDynamicSharedMemorySize, GEMM_SMEM);

    const size_t T = (size_t)B_ * LQ_ * D_;

    // 1) prep:
    //    py (scratch) = rna(Wq)  [NO transpose -- the NT GEMM transposes Bt itself]
    //    Mt = rna(Wk) @ rna(Wq)^T -> g_wt slot0 ; Wv^T rounded -> slot1 ; biases+rsum ; w ; beta+Kr
    round_copy_k<<<(D_ * D_ / 4 + 255) / 256, 256>>>(Wq, py, D_ * D_ / 4);
    gemm_tf32<false, true, false, true, false, false, false><<<dim3(D_ / BN, D_ / BM, 1), 256, GEMM_SMEM>>>(
        Wk, nullptr, py, nullptr, pwt, nullptr, -1, nullptr, D_, D_, 1.f, 0, 0, 0, 0);
    transpose_round_k<<<dim3(D_ / 32, D_ / 32), 256>>>(Wv, pwt + (size_t)D_ * D_, D_, D_);
    prep_small_k<<<(B_ * LQ_ + 255) / 256, 256>>>(bv, pbias, prs);
    matvec_w_k<<<D_ / 2, 256>>>(Wk, bq, pw);
    beta_k<<<(B_ * LK_) / 8, 256>>>(k_in, pw, pbeta, pkr);

    // 2) projections: z=0: Y = rna(Xq) @ M -> g_y ; z=1: V = rna(Xv) @ Wv^T + bv -> g_vt (transposed)
    gemm_tf32<true, true, true, true, true, false, false><<<dim3(D_ / BN, (B_ * LQ_) / BM, 2), 256, GEMM_SMEM>>>(
        q_in, v_in, pwt, pbias, py, pvt, /*zTrans=*/1, nullptr, D_, D_, 1.f,
        0, (size_t)D_ * D_, T, D_);

    // 3) scores: P~ = rna(exp(Y @ Kr^T / 32 + beta)) ; row sums -> g_rsum (atomics)
    gemm_tf32<false, false, true, true, false, true, false><<<dim3(LK_ / BN, LQ_ / BM, B_), 256, GEMM_SMEM>>>(
        py, nullptr, pkr, pbeta, ps, nullptr, -1, prs,
        LK_, D_, 1.f / 32.f,
        (size_t)LQ_ * D_, (size_t)LK_ * D_, (size_t)LQ_ * LK_, LK_);

    // 4) O = (P~ @ V) / rsum  (V^T is [D, LK] K-major; row-normalize in epilogue)
    gemm_tf32<false, false, false, false, false, false, true><<<dim3(D_ / BN, LQ_ / BM, B_), 256, GEMM_SMEM>>>(
        ps, nullptr, pvt, nullptr, out, nullptr, -1, prs,
        D_, LK_, 1.f,
        (size_t)LQ_ * LK_, (size_t)D_ * LK_, (size_t)LQ_ * D_, 0);
}

// round 14
// speedup vs baseline: 1.2919x; 1.0003x over previous
#include <cuda_runtime.h>
#include <cstdint>

#define B_  4
#define LQ_ 2048
#define LK_ 2048
#define D_  1024

// ---------------- scratch (static device globals; no runtime alloc) ----------
__device__ float g_wt  [(size_t)2 * D_ * D_];        // slot0: Mt=Wk@Wq^T ; slot1: Wv^T
__device__ float g_bias[2 * D_];                     // slot0: zeros ; slot1: bv
__device__ float g_y   [(size_t)B_ * LQ_ * D_];      // Y = Xq @ M (tf32-rounded)
__device__ float g_kr  [(size_t)B_ * LK_ * D_];      // tf32-rounded k_in
__device__ float g_vt  [(size_t)B_ * D_ * LK_];      // V^T per batch (tf32-rounded)
__device__ float g_s   [(size_t)B_ * LQ_ * LK_];     // unnormalized exp scores
__device__ float g_w   [D_];                         // w = Wk @ bq
__device__ float g_beta[(size_t)B_ * LK_];           // beta_j / 32 per key position
__device__ float g_rsum[(size_t)B_ * LQ_];           // row sums of exp scores

// ---------------- PTX helpers ------------------------------------------------
__device__ __forceinline__ uint32_t smem_u32(const void* p) {
    uint32_t a;
    asm("{ .reg .u64 t; cvta.to.shared.u64 t, %1; cvt.u32.u64 %0, t; }" : "=r"(a) : "l"(p));
    return a;
}
__device__ __forceinline__ float rna_tf32(float x) {
    uint32_t r; asm("cvt.rna.tf32.f32 %0, %1;" : "=r"(r) : "f"(x));
    return __uint_as_float(r);
}
__device__ __forceinline__ uint32_t rna_tf32_u(uint32_t x) {
    uint32_t r; asm("cvt.rna.tf32.f32 %0, %1;" : "=r"(r) : "f"(__uint_as_float(x)));
    return r;
}
__device__ __forceinline__ void cp16(uint32_t s, const void* g) {
    asm volatile("cp.async.cg.shared.global [%0], [%1], 16;" :: "r"(s), "l"(g));
}
#define CP_COMMIT() asm volatile("cp.async.commit_group;" ::: "memory")
#define CP_WAIT(n)  asm volatile("cp.async.wait_group %0;" :: "n"(n) : "memory")

__device__ __forceinline__ void ldsm4(uint32_t* r, uint32_t addr) {
    asm volatile("ldmatrix.sync.aligned.m8n8.x4.shared.b16 {%0,%1,%2,%3}, [%4];"
        : "=r"(r[0]), "=r"(r[1]), "=r"(r[2]), "=r"(r[3]) : "r"(addr));
}

__device__ __forceinline__ void mma_tf32(float* c, const uint32_t* a, const uint32_t* b) {
    asm volatile(
        "mma.sync.aligned.m16n8k8.row.col.f32.tf32.tf32.f32 "
        "{%0,%1,%2,%3}, {%4,%5,%6,%7}, {%8,%9}, {%0,%1,%2,%3};"
        : "+f"(c[0]), "+f"(c[1]), "+f"(c[2]), "+f"(c[3])
        : "r"(a[0]), "r"(a[1]), "r"(a[2]), "r"(a[3]), "r"(b[0]), "r"(b[1]));
}

// ---------------- tf32 mma.sync NT GEMM --------------------------------------
// C[M,N] = alpha * A[M,K] @ Bt[N,K]^T (+ bias), batched via blockIdx.z.
// Block tile 128x128x32; 256 threads = 8 warps in 4(M) x 2(N); warp tile 32x64.
// RND_A/RND_B: rna-round A/B fragments in-register (raw fp32 operands).
// EXP: epilogue applies expf and atomically accumulates row sums into rsum.
// SCALE: epilogue multiplies rows by 1/rsum[row] (PV normalization).
// TRANSC: for z==zTrans, epilogue writes C transposed into Ct ([D, LK] per batch).
#define BM 128
#define BN 128
#define BK 32
#define RST 36
#define STAGE_FLOATS ((BM + BN) * RST)   // 9216 floats = 36864 B
#define STAGES 3
#define GEMM_SMEM (STAGES * STAGE_FLOATS * 4)

template <bool MULTI_A, bool RND_A, bool RND_B, bool BIAS, bool ROUND, bool TRANSC, bool EXP, bool SCALE>
__global__ __launch_bounds__(256, 2)
void gemm_tf32(const float* __restrict__ A0, const float* __restrict__ A1,
               const float* __restrict__ Bt,
               const float* __restrict__ bias, float* __restrict__ C,
               float* __restrict__ Ct, int zTrans, float* __restrict__ rsum,
               int N, int K, float alpha,
               size_t sA, size_t sB, size_t sC, int sBias)
{
    extern __shared__ float smf[];
    const uint32_t sb32 = smem_u32(smf);

    const int tid  = threadIdx.x;
    const int wid  = tid >> 5;
    const int lane = tid & 31;
    const int grp  = lane >> 2;   // 0..7
    const int q    = lane & 3;    // 0..3
    const int wm   = wid & 3;     // 4 warps along M -> 32 rows each
    const int wn   = wid >> 2;    // 2 warps along N -> 64 cols each

    const int m0 = blockIdx.y * BM;
    const int n0 = blockIdx.x * BN;
    const int z  = blockIdx.z;

    const float* Ab = MULTI_A ? (z == 0 ? A0 : A1) : A0 + (size_t)z * sA;
    const float* Bb = Bt + (size_t)z * sB;
    const float* biasb = BIAS ? (bias + (size_t)z * sBias) : nullptr;
    float* Cb = C + (size_t)z * sC;

    const int KT = K / BK;

    // per-lane ldmatrix byte offsets
    const uint32_t aoff =
        ((wm * 32 + (lane & 7) + ((lane >> 3) & 1) * 8) * RST + ((lane >> 4) & 1) * 4) * 4;
    const uint32_t boff =
        ((wn * 64 + (lane & 7) + ((lane >> 4) & 1) * 8) * RST + ((lane >> 3) & 1) * 4) * 4;

    // async load of one stage: A 128x32 + B 128x32, K-major rows (8 x 16B segs)
    auto load_stage = [&](int s, int kt) {
        const uint32_t abase = sb32 + s * STAGE_FLOATS * 4;
        const uint32_t bbase = abase + BM * RST * 4;
        const int k0 = kt * BK;
#pragma unroll
        for (int j = 0; j < 4; j++) {
            const int idx = tid + j * 256;          // 0..1023
            const int row = idx >> 3, seg = idx & 7;
            cp16(abase + (row * RST + seg * 4) * 4,
                 Ab + (size_t)(m0 + row) * K + k0 + seg * 4);
        }
#pragma unroll
        for (int j = 0; j < 4; j++) {
            const int idx = tid + j * 256;
            const int row = idx >> 3, seg = idx & 7;
            cp16(bbase + (row * RST + seg * 4) * 4,
                 Bb + (size_t)(n0 + row) * K + k0 + seg * 4);
        }
        CP_COMMIT();
    };

    float acc[2][8][4];
#pragma unroll
    for (int i = 0; i < 2; i++)
#pragma unroll
        for (int j = 0; j < 8; j++)
#pragma unroll
            for (int r = 0; r < 4; r++) acc[i][j][r] = 0.f;

    load_stage(0, 0);
    load_stage(1, 1);

    for (int kt = 0; kt < KT; kt++) {
        const int s = kt % STAGES;
        if (kt < KT - 1) { CP_WAIT(1); } else { CP_WAIT(0); }
        __syncthreads();

        if (kt + 2 < KT) load_stage((kt + 2) % STAGES, kt + 2);

        const uint32_t sa = sb32 + s * STAGE_FLOATS * 4;
        const uint32_t sbB = sa + BM * RST * 4;

#pragma unroll
        for (int kk = 0; kk < 4; kk++) {
            uint32_t af[2][4], bf[4][4];
#pragma unroll
            for (int mt = 0; mt < 2; mt++)
                ldsm4(af[mt], sa + aoff + mt * (16 * RST * 4) + kk * 32);
            if (RND_A) {
#pragma unroll
                for (int mt = 0; mt < 2; mt++)
#pragma unroll
                    for (int r = 0; r < 4; r++) af[mt][r] = rna_tf32_u(af[mt][r]);
            }
#pragma unroll
            for (int ntp = 0; ntp < 4; ntp++)
                ldsm4(bf[ntp], sbB + boff + ntp * (16 * RST * 4) + kk * 32);
            if (RND_B) {
#pragma unroll
                for (int ntp = 0; ntp < 4; ntp++)
#pragma unroll
                    for (int r = 0; r < 4; r++) bf[ntp][r] = rna_tf32_u(bf[ntp][r]);
            }
#pragma unroll
            for (int mt = 0; mt < 2; mt++)
#pragma unroll
                for (int nt = 0; nt < 8; nt++)
                    mma_tf32(acc[mt][nt], af[mt], bf[nt >> 1] + (nt & 1) * 2);
        }
    }

    // Epilogue
    const bool doTrans = TRANSC && (z == zTrans);
#pragma unroll
    for (int mt = 0; mt < 2; mt++) {
        const int r = m0 + wm * 32 + mt * 16 + grp;
        float rs0 = 0.f, rs1 = 0.f;     // EXP: row-sum partials
        float inv0 = 1.f, inv1 = 1.f;   // SCALE: row normalizers
        if (SCALE) {
            inv0 = 1.f / rsum[(size_t)z * LQ_ + r];
            inv1 = 1.f / rsum[(size_t)z * LQ_ + r + 8];
        }
#pragma unroll
        for (int nt = 0; nt < 8; nt++) {
            const int c = n0 + wn * 64 + nt * 8 + q * 2;
            float2 v0, v1;
            v0.x = acc[mt][nt][0] * alpha;
            v0.y = acc[mt][nt][1] * alpha;
            v1.x = acc[mt][nt][2] * alpha;
            v1.y = acc[mt][nt][3] * alpha;
            if (BIAS) {
                const float2 bb = *(const float2*)(biasb + c);
                v0.x += bb.x; v0.y += bb.y;
                v1.x += bb.x; v1.y += bb.y;
            }
            if (EXP) {
                v0.x = __expf(v0.x); v0.y = __expf(v0.y);
                v1.x = __expf(v1.x); v1.y = __expf(v1.y);
            }
            if (SCALE) {
                v0.x *= inv0; v0.y *= inv0;
                v1.x *= inv1; v1.y *= inv1;
            }
            if (ROUND) {
                v0.x = rna_tf32(v0.x); v0.y = rna_tf32(v0.y);
                v1.x = rna_tf32(v1.x); v1.y = rna_tf32(v1.y);
            }
            if (EXP) {
                rs0 += v0.x + v0.y;
                rs1 += v1.x + v1.y;
            }
            if (doTrans) {
                const int b0 = r >> 11,       l0 = r & 2047;
                const int b1 = (r + 8) >> 11, l1 = (r + 8) & 2047;
                float* t0 = Ct + (size_t)b0 * D_ * LK_ + l0;
                float* t1 = Ct + (size_t)b1 * D_ * LK_ + l1;
                t0[(size_t)(c)     * LK_] = v0.x;
                t0[(size_t)(c + 1) * LK_] = v0.y;
                t1[(size_t)(c)     * LK_] = v1.x;
                t1[(size_t)(c + 1) * LK_] = v1.y;
            } else {
                *(float2*)(Cb + (size_t)r * N + c)       = v0;
                *(float2*)(Cb + (size_t)(r + 8) * N + c) = v1;
            }
        }
        if (EXP) {
            rs0 += __shfl_xor_sync(0xFFFFFFFFu, rs0, 1);
            rs0 += __shfl_xor_sync(0xFFFFFFFFu, rs0, 2);
            rs1 += __shfl_xor_sync(0xFFFFFFFFu, rs1, 1);
            rs1 += __shfl_xor_sync(0xFFFFFFFFu, rs1, 2);
            if (q == 0) {
                atomicAdd(rsum + (size_t)z * LQ_ + r,     rs0);
                atomicAdd(rsum + (size_t)z * LQ_ + r + 8, rs1);
            }
        }
    }
}

// ---------------- fused prep kernel ------------------------------------------
// Block ranges (grid.x = 1568, 256 threads):
//   [0, 1024):    transpose+round Wv [D,D] -> g_wt slot1  (32x32 tiles)
//   [1024, 1056): bias init (slot0=0, slot1=bv) + rsum zero
//   [1056, 1568): matvec w = Wk @ bq  (2 rows per block, 128 threads each)
__global__ __launch_bounds__(256)
void prep_fused_k(const float* __restrict__ Wv, const float* __restrict__ bv,
                  const float* __restrict__ Wk, const float* __restrict__ bq,
                  float* __restrict__ wvt, float* __restrict__ bias_out,
                  float* __restrict__ rsum, float* __restrict__ w)
{
    __shared__ float t[32][33];
    const int bx = blockIdx.x;

    if (bx < 1024) {
        const int c0 = (bx & 31) * 32, r0 = (bx >> 5) * 32;
        const int tx = threadIdx.x & 31, ty = threadIdx.x >> 5;
#pragma unroll
        for (int i = 0; i < 32; i += 8)
            t[ty + i][tx] = Wv[(size_t)(r0 + ty + i) * D_ + c0 + tx];
        __syncthreads();
#pragma unroll
        for (int i = 0; i < 32; i += 8)
            wvt[(size_t)(c0 + ty + i) * D_ + r0 + tx] = rna_tf32(t[tx][ty + i]);
    } else if (bx < 1056) {
        const int i = (bx - 1024) * 256 + threadIdx.x;   // 0..8191
        if (i < D_)           bias_out[i] = 0.f;
        else if (i < 2 * D_)  bias_out[i] = bv[i - D_];
        rsum[i] = 0.f;
    } else {
        const int sub = threadIdx.x >> 7;                 // 2 rows per block
        const int tt  = threadIdx.x & 127;
        const int row = (bx - 1056) * 2 + sub;
        const float* p = Wk + (size_t)row * D_;
        float s = 0.f;
        for (int i = tt * 4; i < D_; i += 512) {
            const float4 a = *(const float4*)(p + i);
            const float4 b = *(const float4*)(bq + i);
            s += a.x * b.x + a.y * b.y + a.z * b.z + a.w * b.w;
        }
#pragma unroll
        for (int o = 16; o; o >>= 1) s += __shfl_xor_sync(0xFFFFFFFFu, s, o);
        if ((tt & 31) == 0) t[sub][tt >> 5] = s;
        __syncthreads();
        if (tt == 0) w[row] = t[sub][0] + t[sub][1] + t[sub][2] + t[sub][3];
    }
}

// beta[row] = (Xk[row,:] . w) / 32 ; also writes tf32-rounded Xk into kr.
__global__ __launch_bounds__(256)
void beta_k(const float* __restrict__ xk, const float* __restrict__ w,
            float* __restrict__ beta, float* __restrict__ kr)
{
    const int row  = blockIdx.x * 8 + (threadIdx.x >> 5);
    const int lane = threadIdx.x & 31;
    const float* p = xk + (size_t)row * D_;
    float*       o = kr + (size_t)row * D_;
    float s = 0.f;
    for (int i = lane * 4; i < D_; i += 128) {
        float4 a = *(const float4*)(p + i);
        const float4 b = *(const float4*)(w + i);
        s += a.x * b.x + a.y * b.y + a.z * b.z + a.w * b.w;
        a.x = rna_tf32(a.x); a.y = rna_tf32(a.y);
        a.z = rna_tf32(a.z); a.w = rna_tf32(a.w);
        *(float4*)(o + i) = a;
    }
#pragma unroll
    for (int of = 16; of; of >>= 1) s += __shfl_xor_sync(0xFFFFFFFFu, s, of);
    if (lane == 0) beta[row] = s * (1.f / 32.f);
}

// ---------------- host -------------------------------------------------------
extern "C" void kernel_launch(void* const* d_in, const int* in_sizes, int n_in,
                              void* d_out, int out_size)
{
    const float* q_in = (const float*)d_in[0];
    const float* k_in = (const float*)d_in[1];
    const float* v_in = (const float*)d_in[2];
    const float* Wq   = (const float*)d_in[3];
    const float* bq   = (const float*)d_in[4];
    const float* Wk   = (const float*)d_in[5];
    // bk (d_in[6]) cancels in row-softmax; unused.
    const float* Wv   = (const float*)d_in[7];
    const float* bv   = (const float*)d_in[8];
    float* out = (float*)d_out;

    float *pwt, *pbias, *py, *pkr, *pvt, *ps, *pw, *pbeta, *prs;
    cudaGetSymbolAddress((void**)&pwt,   g_wt);
    cudaGetSymbolAddress((void**)&pbias, g_bias);
    cudaGetSymbolAddress((void**)&py,    g_y);
    cudaGetSymbolAddress((void**)&pkr,   g_kr);
    cudaGetSymbolAddress((void**)&pvt,   g_vt);
    cudaGetSymbolAddress((void**)&ps,    g_s);
    cudaGetSymbolAddress((void**)&pw,    g_w);
    cudaGetSymbolAddress((void**)&pbeta, g_beta);
    cudaGetSymbolAddress((void**)&prs,   g_rsum);

    cudaFuncSetAttribute((const void*)gemm_tf32<false, true,  true,  false, true,  false, false, false>,
                         cudaFuncAttributeMaxDynamicSharedMemorySize, GEMM_SMEM);
    cudaFuncSetAttribute((const void*)gemm_tf32<true,  true,  false, true,  true,  true,  false, false>,
                         cudaFuncAttributeMaxDynamicSharedMemorySize, GEMM_SMEM);
    cudaFuncSetAttribute((const void*)gemm_tf32<false, false, false, true,  true,  false, true,  false>,
                         cudaFuncAttributeMaxDynamicSharedMemorySize, GEMM_SMEM);
    cudaFuncSetAttribute((const void*)gemm_tf32<false, false, false, false, false, false, false, true >,
                         cudaFuncAttributeMaxDynamicSharedMemorySize, GEMM_SMEM);

    const size_t T = (size_t)B_ * LQ_ * D_;

    // 1) fused prep: Wv^T rounded -> g_wt slot1 ; biases+rsum ; w = Wk@bq
    prep_fused_k<<<1568, 256>>>(Wv, bv, Wk, bq,
                                pwt + (size_t)D_ * D_, pbias, prs, pw);

    // 2) beta + rounded Kr (needs w)
    beta_k<<<(B_ * LK_) / 8, 256>>>(k_in, pw, pbeta, pkr);

    // 3) Mt = rna(Wk) @ rna(Wq)^T -> g_wt slot0  (raw operands, in-fragment rounding)
    gemm_tf32<false, true, true, false, true, false, false, false>
        <<<dim3(D_ / BN, D_ / BM, 1), 256, GEMM_SMEM>>>(
        Wk, nullptr, Wq, nullptr, pwt, nullptr, -1, nullptr, D_, D_, 1.f, 0, 0, 0, 0);

    // 4) projections: z=0: Y = rna(Xq) @ Mt^T -> g_y ; z=1: V = rna(Xv) @ Wv^T + bv -> g_vt (transposed)
    gemm_tf32<true, true, false, true, true, true, false, false>
        <<<dim3(D_ / BN, (B_ * LQ_) / BM, 2), 256, GEMM_SMEM>>>(
        q_in, v_in, pwt, pbias, py, pvt, /*zTrans=*/1, nullptr, D_, D_, 1.f,
        0, (size_t)D_ * D_, T, D_);

    // 5) scores: P~ = rna(exp(Y @ Kr^T / 32 + beta)) ; row sums -> g_rsum (atomics)
    gemm_tf32<false, false, false, true, true, false, true, false>
        <<<dim3(LK_ / BN, LQ_ / BM, B_), 256, GEMM_SMEM>>>(
        py, nullptr, pkr, pbeta, ps, nullptr, -1, prs,
        LK_, D_, 1.f / 32.f,
        (size_t)LQ_ * D_, (size_t)LK_ * D_, (size_t)LQ_ * LK_, LK_);

    // 6) O = (P~ @ V) / rsum  (V^T is [D, LK] K-major; row-normalize in epilogue)
    gemm_tf32<false, false, false, false, false, false, false, true>
        <<<dim3(D_ / BN, LQ_ / BM, B_), 256, GEMM_SMEM>>>(
        ps, nullptr, pvt, nullptr, out, nullptr, -1, prs,
        D_, LK_, 1.f,
        (size_t)LQ_ * LK_, (size_t)D_ * LK_, (size_t)LQ_ * D_, 0);
}